// round 1
// baseline (speedup 1.0000x reference)
#include <cuda_runtime.h>
#include <math.h>

#define D_MODEL 1024
#define NH 16
#define DK 64
#define BAND 100
#define BB 2
#define SS 2048
#define M_TOT (BB * SS)

// Scratch (device globals — no allocation allowed in kernel_launch)
__device__ float g_Q[BB * NH * SS * DK];   // [B, H, S, DK]
__device__ float g_K[BB * NH * SS * DK];
__device__ float g_V[BB * NH * SS * DK];
__device__ float g_AO[BB * SS * D_MODEL]; // [B, S, D_MODEL] (heads concatenated)

// ---------------------------------------------------------------------------
// SGEMM core: C[M=4096, N=1024] = A[M,1024] @ W[N,1024]^T + bias
// BM=BN=128, BK=8, 256 threads, 8x8 per-thread microtile.
// ---------------------------------------------------------------------------

__global__ __launch_bounds__(256) void qkv_gemm(
    const float* __restrict__ x,
    const float* __restrict__ Wq, const float* __restrict__ Wk, const float* __restrict__ Wv,
    const float* __restrict__ bq, const float* __restrict__ bk, const float* __restrict__ bv)
{
    __shared__ float As[8][132];
    __shared__ float Bs[8][132];

    const int z = blockIdx.z;
    const float* W    = (z == 0) ? Wq : (z == 1) ? Wk : Wv;
    const float* bias = (z == 0) ? bq : (z == 1) ? bk : bv;
    float* dst        = (z == 0) ? g_Q : (z == 1) ? g_K : g_V;

    const int bm = blockIdx.y * 128;
    const int bn = blockIdx.x * 128;
    const int tid = threadIdx.x;
    const int tx = tid & 15, ty = tid >> 4;
    const int lr = tid >> 1;            // 0..127
    const int lk = (tid & 1) * 4;       // 0 or 4

    float acc[8][8];
#pragma unroll
    for (int i = 0; i < 8; i++)
#pragma unroll
        for (int j = 0; j < 8; j++) acc[i][j] = 0.f;

    for (int kt = 0; kt < D_MODEL; kt += 8) {
        float4 av = *(const float4*)&x[(size_t)(bm + lr) * D_MODEL + kt + lk];
        float4 wv = *(const float4*)&W[(size_t)(bn + lr) * D_MODEL + kt + lk];
        As[lk + 0][lr] = av.x; As[lk + 1][lr] = av.y; As[lk + 2][lr] = av.z; As[lk + 3][lr] = av.w;
        Bs[lk + 0][lr] = wv.x; Bs[lk + 1][lr] = wv.y; Bs[lk + 2][lr] = wv.z; Bs[lk + 3][lr] = wv.w;
        __syncthreads();
#pragma unroll
        for (int k = 0; k < 8; k++) {
            float a[8], b[8];
            *(float4*)&a[0] = *(const float4*)&As[k][ty * 8];
            *(float4*)&a[4] = *(const float4*)&As[k][ty * 8 + 4];
            *(float4*)&b[0] = *(const float4*)&Bs[k][tx * 8];
            *(float4*)&b[4] = *(const float4*)&Bs[k][tx * 8 + 4];
#pragma unroll
            for (int i = 0; i < 8; i++)
#pragma unroll
                for (int j = 0; j < 8; j++) acc[i][j] += a[i] * b[j];
        }
        __syncthreads();
    }

    // Epilogue: split heads — dst[((b*H+h)*S + s)*DK + d]
    const int n0 = bn + tx * 8;
    const int h = n0 >> 6;
    const int d0 = n0 & 63;
    float bb0[8];
#pragma unroll
    for (int j = 0; j < 8; j++) bb0[j] = bias[n0 + j];

#pragma unroll
    for (int i = 0; i < 8; i++) {
        int m = bm + ty * 8 + i;
        int b_ = m >> 11;
        int s_ = m & (SS - 1);
        float* p = &dst[((((size_t)b_ * NH + h) * SS) + s_) * DK + d0];
        float4 v0 = make_float4(acc[i][0] + bb0[0], acc[i][1] + bb0[1],
                                acc[i][2] + bb0[2], acc[i][3] + bb0[3]);
        float4 v1 = make_float4(acc[i][4] + bb0[4], acc[i][5] + bb0[5],
                                acc[i][6] + bb0[6], acc[i][7] + bb0[7]);
        *(float4*)&p[0] = v0;
        *(float4*)&p[4] = v1;
    }
}

__global__ __launch_bounds__(256) void out_gemm(
    const float* __restrict__ Wo, const float* __restrict__ bo, float* __restrict__ C)
{
    __shared__ float As[8][132];
    __shared__ float Bs[8][132];

    const float* A = g_AO;
    const int bm = blockIdx.y * 128;
    const int bn = blockIdx.x * 128;
    const int tid = threadIdx.x;
    const int tx = tid & 15, ty = tid >> 4;
    const int lr = tid >> 1;
    const int lk = (tid & 1) * 4;

    float acc[8][8];
#pragma unroll
    for (int i = 0; i < 8; i++)
#pragma unroll
        for (int j = 0; j < 8; j++) acc[i][j] = 0.f;

    for (int kt = 0; kt < D_MODEL; kt += 8) {
        float4 av = *(const float4*)&A[(size_t)(bm + lr) * D_MODEL + kt + lk];
        float4 wv = *(const float4*)&Wo[(size_t)(bn + lr) * D_MODEL + kt + lk];
        As[lk + 0][lr] = av.x; As[lk + 1][lr] = av.y; As[lk + 2][lr] = av.z; As[lk + 3][lr] = av.w;
        Bs[lk + 0][lr] = wv.x; Bs[lk + 1][lr] = wv.y; Bs[lk + 2][lr] = wv.z; Bs[lk + 3][lr] = wv.w;
        __syncthreads();
#pragma unroll
        for (int k = 0; k < 8; k++) {
            float a[8], b[8];
            *(float4*)&a[0] = *(const float4*)&As[k][ty * 8];
            *(float4*)&a[4] = *(const float4*)&As[k][ty * 8 + 4];
            *(float4*)&b[0] = *(const float4*)&Bs[k][tx * 8];
            *(float4*)&b[4] = *(const float4*)&Bs[k][tx * 8 + 4];
#pragma unroll
            for (int i = 0; i < 8; i++)
#pragma unroll
                for (int j = 0; j < 8; j++) acc[i][j] += a[i] * b[j];
        }
        __syncthreads();
    }

    const int n0 = bn + tx * 8;
    float bb0[8];
#pragma unroll
    for (int j = 0; j < 8; j++) bb0[j] = bo[n0 + j];

#pragma unroll
    for (int i = 0; i < 8; i++) {
        int m = bm + ty * 8 + i;
        float* p = &C[(size_t)m * D_MODEL + n0];
        float4 v0 = make_float4(acc[i][0] + bb0[0], acc[i][1] + bb0[1],
                                acc[i][2] + bb0[2], acc[i][3] + bb0[3]);
        float4 v1 = make_float4(acc[i][4] + bb0[4], acc[i][5] + bb0[5],
                                acc[i][6] + bb0[6], acc[i][7] + bb0[7]);
        *(float4*)&p[0] = v0;
        *(float4*)&p[4] = v1;
    }
}

// ---------------------------------------------------------------------------
// Banded flash attention: block = (64 queries) x (one b,h). Key tiles of 32.
// Thread layout 16x16: each thread owns 4 queries x (2 score keys / 4 out dims).
// ---------------------------------------------------------------------------

__global__ __launch_bounds__(256) void band_attn()
{
    __shared__ float Qst[DK][68];   // [d][q]   (Q transposed)
    __shared__ float Kst[DK][36];   // [d][key] (K transposed), 32 keys
    __shared__ float Vs[32][68];    // [key][d]
    __shared__ float Pst[32][68];   // [key][q] (P transposed)

    const int q0 = blockIdx.x * 64;
    const int h = blockIdx.y;
    const int b = blockIdx.z;
    const int tid = threadIdx.x;
    const int tx = tid & 15, ty = tid >> 4;

    const size_t head_off = (((size_t)b * NH + h) * SS) * DK;
    const float* Qg = &g_Q[head_off];
    const float* Kg = &g_K[head_off];
    const float* Vg = &g_V[head_off];

    // Load Q tile (64 x 64), transposed into smem
    for (int t = tid; t < 64 * 16; t += 256) {
        int q = t >> 4;
        int d0 = (t & 15) * 4;
        float4 v = *(const float4*)&Qg[(size_t)(q0 + q) * DK + d0];
        Qst[d0 + 0][q] = v.x; Qst[d0 + 1][q] = v.y;
        Qst[d0 + 2][q] = v.z; Qst[d0 + 3][q] = v.w;
    }

    float o[4][4];
    float mrow[4], lrow[4];
#pragma unroll
    for (int i = 0; i < 4; i++) {
        mrow[i] = -1e9f; lrow[i] = 0.f;
#pragma unroll
        for (int j = 0; j < 4; j++) o[i][j] = 0.f;
    }

    int lo = q0 - (BAND - 1); if (lo < 0) lo = 0;
    int hi = q0 + 63 + (BAND - 1); if (hi > SS - 1) hi = SS - 1;
    const int kt_lo = lo >> 5, kt_hi = hi >> 5;

    for (int kt = kt_lo; kt <= kt_hi; kt++) {
        const int kbase = kt * 32;
        // Load K tile (32 x 64) transposed + V tile (32 x 64) natural
        for (int t = tid; t < 32 * 16; t += 256) {
            int kk = t >> 4;
            int d0 = (t & 15) * 4;
            float4 kv = *(const float4*)&Kg[(size_t)(kbase + kk) * DK + d0];
            Kst[d0 + 0][kk] = kv.x; Kst[d0 + 1][kk] = kv.y;
            Kst[d0 + 2][kk] = kv.z; Kst[d0 + 3][kk] = kv.w;
            float4 vv = *(const float4*)&Vg[(size_t)(kbase + kk) * DK + d0];
            *(float4*)&Vs[kk][d0] = vv;
        }
        __syncthreads();

        // Scores: 4 queries x 2 keys per thread
        float sc[4][2];
#pragma unroll
        for (int i = 0; i < 4; i++) { sc[i][0] = 0.f; sc[i][1] = 0.f; }
#pragma unroll 8
        for (int d = 0; d < DK; d++) {
            float qv[4];
            *(float4*)qv = *(const float4*)&Qst[d][ty * 4];
            float k0 = Kst[d][tx * 2 + 0];
            float k1 = Kst[d][tx * 2 + 1];
#pragma unroll
            for (int i = 0; i < 4; i++) {
                sc[i][0] += qv[i] * k0;
                sc[i][1] += qv[i] * k1;
            }
        }
        // Scale + band mask
#pragma unroll
        for (int i = 0; i < 4; i++) {
            int qi = q0 + ty * 4 + i;
#pragma unroll
            for (int j = 0; j < 2; j++) {
                int kj = kbase + tx * 2 + j;
                float s = sc[i][j] * 0.125f;
                int dqk = qi - kj; if (dqk < 0) dqk = -dqk;
                sc[i][j] = (dqk >= BAND) ? -1e9f : s;
            }
        }
        // Online softmax: row reductions across 16 lanes (same ty)
        float p[4][2];
#pragma unroll
        for (int i = 0; i < 4; i++) {
            float tmax = fmaxf(sc[i][0], sc[i][1]);
#pragma unroll
            for (int off = 1; off < 16; off <<= 1)
                tmax = fmaxf(tmax, __shfl_xor_sync(0xffffffffu, tmax, off));
            float mnew = fmaxf(mrow[i], tmax);
            float scale = __expf(mrow[i] - mnew);
            mrow[i] = mnew;
            p[i][0] = __expf(sc[i][0] - mnew);
            p[i][1] = __expf(sc[i][1] - mnew);
            float psum = p[i][0] + p[i][1];
#pragma unroll
            for (int off = 1; off < 16; off <<= 1)
                psum += __shfl_xor_sync(0xffffffffu, psum, off);
            lrow[i] = lrow[i] * scale + psum;
#pragma unroll
            for (int j = 0; j < 4; j++) o[i][j] *= scale;
            Pst[tx * 2 + 0][ty * 4 + i] = p[i][0];
            Pst[tx * 2 + 1][ty * 4 + i] = p[i][1];
        }
        __syncthreads();

        // O += P @ V   (4 queries x 4 dims per thread)
#pragma unroll 8
        for (int kk = 0; kk < 32; kk++) {
            float pr[4], vv[4];
            *(float4*)pr = *(const float4*)&Pst[kk][ty * 4];
            *(float4*)vv = *(const float4*)&Vs[kk][tx * 4];
#pragma unroll
            for (int i = 0; i < 4; i++)
#pragma unroll
                for (int j = 0; j < 4; j++) o[i][j] += pr[i] * vv[j];
        }
        __syncthreads();
    }

    // Write attention output, heads concatenated: [B, S, D_MODEL]
#pragma unroll
    for (int i = 0; i < 4; i++) {
        int q = q0 + ty * 4 + i;
        float inv = 1.0f / lrow[i];
        float4 r = make_float4(o[i][0] * inv, o[i][1] * inv, o[i][2] * inv, o[i][3] * inv);
        *(float4*)&g_AO[((size_t)(b * SS + q)) * D_MODEL + h * DK + tx * 4] = r;
    }
}

// ---------------------------------------------------------------------------

extern "C" void kernel_launch(void* const* d_in, const int* in_sizes, int n_in,
                              void* d_out, int out_size)
{
    const float* x  = (const float*)d_in[0];
    const float* Wq = (const float*)d_in[1];
    const float* bq = (const float*)d_in[2];
    const float* Wk = (const float*)d_in[3];
    const float* bk = (const float*)d_in[4];
    const float* Wv = (const float*)d_in[5];
    const float* bv = (const float*)d_in[6];
    const float* Wo = (const float*)d_in[7];
    const float* bo = (const float*)d_in[8];
    float* out = (float*)d_out;

    // 1) Fused QKV projections (z selects Q/K/V weight)
    qkv_gemm<<<dim3(D_MODEL / 128, M_TOT / 128, 3), 256>>>(x, Wq, Wk, Wv, bq, bk, bv);
    // 2) Banded attention
    band_attn<<<dim3(SS / 64, NH, BB), 256>>>();
    // 3) Output projection
    out_gemm<<<dim3(D_MODEL / 128, M_TOT / 128, 1), 256>>>(Wo, bo, out);
}

// round 3
// speedup vs baseline: 1.8696x; 1.8696x over previous
#include <cuda_runtime.h>
#include <cuda_bf16.h>
#include <cstdint>
#include <math.h>

#define D_MODEL 1024
#define NH 16
#define DK 64
#define BAND 100
#define BB 2
#define SS 2048
#define M_TOT (BB * SS)
#define DM2 (D_MODEL * D_MODEL)

// ---------------- scratch (device globals; no allocs allowed) ----------------
__device__ __align__(256) float g_Q[BB * NH * SS * DK];
__device__ __align__(256) float g_K[BB * NH * SS * DK];
__device__ __align__(256) float g_V[BB * NH * SS * DK];
__device__ __align__(256) __nv_bfloat16 g_xh[M_TOT * D_MODEL];
__device__ __align__(256) __nv_bfloat16 g_xl[M_TOT * D_MODEL];
__device__ __align__(256) __nv_bfloat16 g_wh[4 * DM2];
__device__ __align__(256) __nv_bfloat16 g_wl[4 * DM2];
__device__ __align__(256) __nv_bfloat16 g_aoh[M_TOT * D_MODEL];
__device__ __align__(256) __nv_bfloat16 g_aol[M_TOT * D_MODEL];

// ---------------- helpers ----------------
__device__ __forceinline__ uint32_t s2u(const void* p) {
    uint32_t a;
    asm("{ .reg .u64 t; cvta.to.shared.u64 t, %1; cvt.u32.u64 %0, t; }" : "=r"(a) : "l"(p));
    return a;
}

// swizzle for 64-byte rows (8-row x 64B atom): xor 16B-column bits with row bits
#define SWZ64(o) ((o) ^ (((o) >> 3) & 0x30))

#define CP16(dst, src) \
    asm volatile("cp.async.cg.shared.global [%0], [%1], 16;" :: "r"(dst), "l"(src))

#define LDSM4(r, addr) \
    asm volatile("ldmatrix.sync.aligned.m8n8.x4.shared.b16 {%0,%1,%2,%3}, [%4];" \
                 : "=r"((r)[0]), "=r"((r)[1]), "=r"((r)[2]), "=r"((r)[3]) : "r"(addr))

#define MMA16816(d, a, bx, by) \
    asm volatile("mma.sync.aligned.m16n8k16.row.col.f32.bf16.bf16.f32 " \
                 "{%0,%1,%2,%3}, {%4,%5,%6,%7}, {%8,%9}, {%0,%1,%2,%3};" \
                 : "+f"((d)[0]), "+f"((d)[1]), "+f"((d)[2]), "+f"((d)[3]) \
                 : "r"((a)[0]), "r"((a)[1]), "r"((a)[2]), "r"((a)[3]), "r"(bx), "r"(by))

// ---------------- fp32 -> bf16 hi/lo splits ----------------
__device__ __forceinline__ void split4(float4 v, uint2& hv, uint2& lv) {
    __nv_bfloat162 h0 = __floats2bfloat162_rn(v.x, v.y);
    __nv_bfloat162 h1 = __floats2bfloat162_rn(v.z, v.w);
    __nv_bfloat162 l0 = __floats2bfloat162_rn(v.x - __bfloat162float(h0.x),
                                              v.y - __bfloat162float(h0.y));
    __nv_bfloat162 l1 = __floats2bfloat162_rn(v.z - __bfloat162float(h1.x),
                                              v.w - __bfloat162float(h1.y));
    hv.x = reinterpret_cast<uint32_t&>(h0); hv.y = reinterpret_cast<uint32_t&>(h1);
    lv.x = reinterpret_cast<uint32_t&>(l0); lv.y = reinterpret_cast<uint32_t&>(l1);
}

__global__ void cvt_x(const float4* __restrict__ src) {
    int i = blockIdx.x * blockDim.x + threadIdx.x;
    if (i >= M_TOT * D_MODEL / 4) return;
    uint2 hv, lv;
    split4(src[i], hv, lv);
    ((uint2*)g_xh)[i] = hv;
    ((uint2*)g_xl)[i] = lv;
}

__global__ void cvt_w(const float4* __restrict__ src, int slot) {
    int i = blockIdx.x * blockDim.x + threadIdx.x;
    if (i >= DM2 / 4) return;
    uint2 hv, lv;
    split4(src[i], hv, lv);
    ((uint2*)g_wh)[(size_t)slot * (DM2 / 4) + i] = hv;
    ((uint2*)g_wl)[(size_t)slot * (DM2 / 4) + i] = lv;
}

// ---------------------------------------------------------------------------
// HMMA 3xBF16 GEMM: C[4096,1024] = A[4096,1024] @ W[1024,1024]^T + bias
// CTA 128x128, 8 warps (4M x 2N, warp tile 32x64), K-chunk 32, cp.async x3.
// mode 0: A = g_xh/g_xl, W slot z, dst g_Q/g_K/g_V with head-split epilogue.
// mode 1: A = g_aoh/g_aol, W slot 3, dst = outp row-major.
// ---------------------------------------------------------------------------
__global__ __launch_bounds__(256, 1) void tc_gemm(
    int mode, const float* __restrict__ b0, const float* __restrict__ b1,
    const float* __restrict__ b2, float* outp)
{
    extern __shared__ char dsm[];
    uint32_t raw = s2u(dsm);
    const uint32_t S = (raw + 1023u) & ~1023u;

    const int tid = threadIdx.x;
    const int lane = tid & 31;
    const int wid = tid >> 5;
    const int wm = wid >> 1;          // 0..3
    const int wn = wid & 1;           // 0..1
    const int bm = blockIdx.y * 128;
    const int bn = blockIdx.x * 128;
    const int z = blockIdx.z;

    const __nv_bfloat16 *Ahp, *Alp, *Whp, *Wlp;
    const float* bias;
    float* dst;
    if (mode == 0) {
        Ahp = g_xh; Alp = g_xl;
        Whp = g_wh + (size_t)z * DM2; Wlp = g_wl + (size_t)z * DM2;
        bias = (z == 0) ? b0 : (z == 1) ? b1 : b2;
        dst = (z == 0) ? g_Q : (z == 1) ? g_K : g_V;
    } else {
        Ahp = g_aoh; Alp = g_aol;
        Whp = g_wh + 3 * (size_t)DM2; Wlp = g_wl + 3 * (size_t)DM2;
        bias = b0;
        dst = outp;
    }

    // cp.async thread mapping: 64 rows x 4 x 16B per shot, two shots per tile
    const int crow = tid >> 2;
    const int ccol = (tid & 3) * 16;                      // byte col in 64B row
    const uint32_t dst0 = SWZ64((uint32_t)(crow * 64 + ccol));
    const uint32_t dst1 = SWZ64((uint32_t)((crow + 64) * 64 + ccol));

    auto issue = [&](int stg, int kt) {
        uint32_t sb = S + (uint32_t)stg * 32768u;
        size_t ra = (size_t)(bm + crow) * D_MODEL + kt + (ccol >> 1);
        size_t rb = (size_t)(bn + crow) * D_MODEL + kt + (ccol >> 1);
        CP16(sb + dst0,          Ahp + ra);
        CP16(sb + dst1,          Ahp + ra + 64 * D_MODEL);
        CP16(sb + 8192 + dst0,   Alp + ra);
        CP16(sb + 8192 + dst1,   Alp + ra + 64 * D_MODEL);
        CP16(sb + 16384 + dst0,  Whp + rb);
        CP16(sb + 16384 + dst1,  Whp + rb + 64 * D_MODEL);
        CP16(sb + 24576 + dst0,  Wlp + rb);
        CP16(sb + 24576 + dst1,  Wlp + rb + 64 * D_MODEL);
        asm volatile("cp.async.commit_group;" ::: "memory");
    };

    // ldmatrix per-thread offsets (within A-hi / B-hi tiles)
    uint32_t aoff[2][2], boff[4][2];
#pragma unroll
    for (int mf = 0; mf < 2; mf++)
#pragma unroll
        for (int kh = 0; kh < 2; kh++) {
            int r = wm * 32 + mf * 16 + (lane & 15);
            aoff[mf][kh] = SWZ64((uint32_t)(r * 64 + kh * 32 + ((lane >> 4) << 4)));
        }
#pragma unroll
    for (int nf = 0; nf < 4; nf++)
#pragma unroll
        for (int kh = 0; kh < 2; kh++) {
            int r = wn * 64 + nf * 16 + (lane & 15);
            boff[nf][kh] = 16384u + SWZ64((uint32_t)(r * 64 + kh * 32 + ((lane >> 4) << 4)));
        }

    float acc[2][8][4];
#pragma unroll
    for (int mf = 0; mf < 2; mf++)
#pragma unroll
        for (int j = 0; j < 8; j++)
#pragma unroll
            for (int t = 0; t < 4; t++) acc[mf][j][t] = 0.f;

    issue(0, 0);
    issue(1, 32);

    for (int i = 0; i < 32; i++) {
        asm volatile("cp.async.wait_group 1;" ::: "memory");
        __syncthreads();
        const uint32_t sb = S + (uint32_t)(((uint32_t)i) % 3u) * 32768u;
        if (i + 2 < 32) issue((i + 2) % 3, (i + 2) * 32);
        else asm volatile("cp.async.commit_group;" ::: "memory");

#pragma unroll
        for (int kh = 0; kh < 2; kh++) {
            uint32_t ah[2][4], al[2][4], bh[4][4], bl[4][4];
#pragma unroll
            for (int mf = 0; mf < 2; mf++) {
                LDSM4(ah[mf], sb + aoff[mf][kh]);
                LDSM4(al[mf], sb + 8192u + aoff[mf][kh]);
            }
#pragma unroll
            for (int nf = 0; nf < 4; nf++) {
                LDSM4(bh[nf], sb + boff[nf][kh]);
                LDSM4(bl[nf], sb + 8192u + boff[nf][kh]);
            }
#pragma unroll
            for (int mf = 0; mf < 2; mf++)
#pragma unroll
                for (int j = 0; j < 8; j++) {
                    const int nf = j >> 1, s0 = j & 1;
                    MMA16816(acc[mf][j], ah[mf], bh[nf][s0], bh[nf][s0 + 2]);
                    MMA16816(acc[mf][j], ah[mf], bl[nf][s0], bl[nf][s0 + 2]);
                    MMA16816(acc[mf][j], al[mf], bh[nf][s0], bh[nf][s0 + 2]);
                }
        }
    }

    // epilogue straight from registers
    const int r0 = lane >> 2;
    const int c0 = (lane & 3) << 1;
#pragma unroll
    for (int mf = 0; mf < 2; mf++) {
        const int m_ = bm + wm * 32 + mf * 16 + r0;
#pragma unroll
        for (int j = 0; j < 8; j++) {
            const int n_ = bn + wn * 64 + j * 8 + c0;
            const float bx = bias[n_], by = bias[n_ + 1];
            float2 v0 = make_float2(acc[mf][j][0] + bx, acc[mf][j][1] + by);
            float2 v1 = make_float2(acc[mf][j][2] + bx, acc[mf][j][3] + by);
            if (mode == 0) {
                const int b_ = m_ >> 11, s_ = m_ & (SS - 1);
                float* p = dst + ((((size_t)b_ * NH + (n_ >> 6)) * SS) + s_) * DK + (n_ & 63);
                *(float2*)p = v0;
                *(float2*)(p + 8 * DK) = v1;
            } else {
                float* p = dst + (size_t)m_ * D_MODEL + n_;
                *(float2*)p = v0;
                *(float2*)(p + 8 * D_MODEL) = v1;
            }
        }
    }
}

// ---------------------------------------------------------------------------
// Banded flash attention (fp32), writes bf16 hi/lo split output.
// ---------------------------------------------------------------------------
__global__ __launch_bounds__(256) void band_attn()
{
    __shared__ float Qst[DK][68];
    __shared__ float Kst[DK][36];
    __shared__ float Vs[32][68];
    __shared__ float Pst[32][68];

    const int q0 = blockIdx.x * 64;
    const int hh = blockIdx.y;
    const int b = blockIdx.z;
    const int tid = threadIdx.x;
    const int tx = tid & 15, ty = tid >> 4;

    const size_t head_off = (((size_t)b * NH + hh) * SS) * DK;
    const float* Qg = &g_Q[head_off];
    const float* Kg = &g_K[head_off];
    const float* Vg = &g_V[head_off];

    for (int t = tid; t < 64 * 16; t += 256) {
        int q = t >> 4;
        int d0 = (t & 15) * 4;
        float4 v = *(const float4*)&Qg[(size_t)(q0 + q) * DK + d0];
        Qst[d0 + 0][q] = v.x; Qst[d0 + 1][q] = v.y;
        Qst[d0 + 2][q] = v.z; Qst[d0 + 3][q] = v.w;
    }

    float o[4][4];
    float mrow[4], lrow[4];
#pragma unroll
    for (int i = 0; i < 4; i++) {
        mrow[i] = -1e9f; lrow[i] = 0.f;
#pragma unroll
        for (int j = 0; j < 4; j++) o[i][j] = 0.f;
    }

    int lo = q0 - (BAND - 1); if (lo < 0) lo = 0;
    int hi = q0 + 63 + (BAND - 1); if (hi > SS - 1) hi = SS - 1;
    const int kt_lo = lo >> 5, kt_hi = hi >> 5;

    for (int kt = kt_lo; kt <= kt_hi; kt++) {
        const int kbase = kt * 32;
        for (int t = tid; t < 32 * 16; t += 256) {
            int kk = t >> 4;
            int d0 = (t & 15) * 4;
            float4 kv = *(const float4*)&Kg[(size_t)(kbase + kk) * DK + d0];
            Kst[d0 + 0][kk] = kv.x; Kst[d0 + 1][kk] = kv.y;
            Kst[d0 + 2][kk] = kv.z; Kst[d0 + 3][kk] = kv.w;
            float4 vv = *(const float4*)&Vg[(size_t)(kbase + kk) * DK + d0];
            *(float4*)&Vs[kk][d0] = vv;
        }
        __syncthreads();

        float sc[4][2];
#pragma unroll
        for (int i = 0; i < 4; i++) { sc[i][0] = 0.f; sc[i][1] = 0.f; }
#pragma unroll 8
        for (int d = 0; d < DK; d++) {
            float qv[4];
            *(float4*)qv = *(const float4*)&Qst[d][ty * 4];
            float k0 = Kst[d][tx * 2 + 0];
            float k1 = Kst[d][tx * 2 + 1];
#pragma unroll
            for (int i = 0; i < 4; i++) {
                sc[i][0] += qv[i] * k0;
                sc[i][1] += qv[i] * k1;
            }
        }
#pragma unroll
        for (int i = 0; i < 4; i++) {
            int qi = q0 + ty * 4 + i;
#pragma unroll
            for (int j = 0; j < 2; j++) {
                int kj = kbase + tx * 2 + j;
                float s = sc[i][j] * 0.125f;
                int dqk = qi - kj; if (dqk < 0) dqk = -dqk;
                sc[i][j] = (dqk >= BAND) ? -1e9f : s;
            }
        }
        float p[4][2];
#pragma unroll
        for (int i = 0; i < 4; i++) {
            float tmax = fmaxf(sc[i][0], sc[i][1]);
#pragma unroll
            for (int off = 1; off < 16; off <<= 1)
                tmax = fmaxf(tmax, __shfl_xor_sync(0xffffffffu, tmax, off));
            float mnew = fmaxf(mrow[i], tmax);
            float scale = __expf(mrow[i] - mnew);
            mrow[i] = mnew;
            p[i][0] = __expf(sc[i][0] - mnew);
            p[i][1] = __expf(sc[i][1] - mnew);
            float psum = p[i][0] + p[i][1];
#pragma unroll
            for (int off = 1; off < 16; off <<= 1)
                psum += __shfl_xor_sync(0xffffffffu, psum, off);
            lrow[i] = lrow[i] * scale + psum;
#pragma unroll
            for (int j = 0; j < 4; j++) o[i][j] *= scale;
            Pst[tx * 2 + 0][ty * 4 + i] = p[i][0];
            Pst[tx * 2 + 1][ty * 4 + i] = p[i][1];
        }
        __syncthreads();

#pragma unroll 8
        for (int kk = 0; kk < 32; kk++) {
            float pr[4], vv[4];
            *(float4*)pr = *(const float4*)&Pst[kk][ty * 4];
            *(float4*)vv = *(const float4*)&Vs[kk][tx * 4];
#pragma unroll
            for (int i = 0; i < 4; i++)
#pragma unroll
                for (int j = 0; j < 4; j++) o[i][j] += pr[i] * vv[j];
        }
        __syncthreads();
    }

#pragma unroll
    for (int i = 0; i < 4; i++) {
        int q = q0 + ty * 4 + i;
        float inv = 1.0f / lrow[i];
        float4 v = make_float4(o[i][0] * inv, o[i][1] * inv, o[i][2] * inv, o[i][3] * inv);
        uint2 hv, lv;
        split4(v, hv, lv);
        size_t e = ((size_t)(b * SS + q)) * D_MODEL + hh * DK + tx * 4;
        *(uint2*)(g_aoh + e) = hv;
        *(uint2*)(g_aol + e) = lv;
    }
}

// ---------------------------------------------------------------------------

extern "C" void kernel_launch(void* const* d_in, const int* in_sizes, int n_in,
                              void* d_out, int out_size)
{
    const float* x  = (const float*)d_in[0];
    const float* Wq = (const float*)d_in[1];
    const float* bq = (const float*)d_in[2];
    const float* Wk = (const float*)d_in[3];
    const float* bk = (const float*)d_in[4];
    const float* Wv = (const float*)d_in[5];
    const float* bv = (const float*)d_in[6];
    const float* Wo = (const float*)d_in[7];
    const float* bo = (const float*)d_in[8];
    float* out = (float*)d_out;

    const int SMEMSZ = 3 * 32768 + 1024;
    static bool attr_done = false;
    if (!attr_done) {
        cudaFuncSetAttribute(tc_gemm, cudaFuncAttributeMaxDynamicSharedMemorySize, SMEMSZ);
        attr_done = true;
    }

    // fp32 -> bf16 hi/lo splits
    cvt_x<<<(M_TOT * D_MODEL / 4 + 255) / 256, 256>>>((const float4*)x);
    cvt_w<<<(DM2 / 4 + 255) / 256, 256>>>((const float4*)Wq, 0);
    cvt_w<<<(DM2 / 4 + 255) / 256, 256>>>((const float4*)Wk, 1);
    cvt_w<<<(DM2 / 4 + 255) / 256, 256>>>((const float4*)Wv, 2);
    cvt_w<<<(DM2 / 4 + 255) / 256, 256>>>((const float4*)Wo, 3);

    // Fused QKV projections (HMMA 3xBF16)
    tc_gemm<<<dim3(D_MODEL / 128, M_TOT / 128, 3), 256, SMEMSZ>>>(0, bq, bk, bv, nullptr);

    // Banded attention
    band_attn<<<dim3(SS / 64, NH, BB), 256>>>();

    // Output projection
    tc_gemm<<<dim3(D_MODEL / 128, M_TOT / 128, 1), 256, SMEMSZ>>>(1, bo, bo, bo, out);
}

// round 4
// speedup vs baseline: 2.7005x; 1.4444x over previous
#include <cuda_runtime.h>
#include <cuda_bf16.h>
#include <cstdint>
#include <math.h>

#define D_MODEL 1024
#define NH 16
#define DK 64
#define BAND 100
#define BB 2
#define SS 2048
#define M_TOT (BB * SS)
#define DM2 (D_MODEL * D_MODEL)

// ---------------- scratch (device globals; no allocs allowed) ----------------
__device__ __align__(256) __nv_bfloat16 g_qh[BB * NH * SS * DK];
__device__ __align__(256) __nv_bfloat16 g_ql[BB * NH * SS * DK];
__device__ __align__(256) __nv_bfloat16 g_kh[BB * NH * SS * DK];
__device__ __align__(256) __nv_bfloat16 g_kl[BB * NH * SS * DK];
__device__ __align__(256) __nv_bfloat16 g_vh[BB * NH * SS * DK];
__device__ __align__(256) __nv_bfloat16 g_vl[BB * NH * SS * DK];
__device__ __align__(256) __nv_bfloat16 g_xh[M_TOT * D_MODEL];
__device__ __align__(256) __nv_bfloat16 g_xl[M_TOT * D_MODEL];
__device__ __align__(256) __nv_bfloat16 g_wh[4 * DM2];
__device__ __align__(256) __nv_bfloat16 g_wl[4 * DM2];
__device__ __align__(256) __nv_bfloat16 g_aoh[M_TOT * D_MODEL];
__device__ __align__(256) __nv_bfloat16 g_aol[M_TOT * D_MODEL];

// ---------------- helpers ----------------
__device__ __forceinline__ uint32_t s2u(const void* p) {
    uint32_t a;
    asm("{ .reg .u64 t; cvta.to.shared.u64 t, %1; cvt.u32.u64 %0, t; }" : "=r"(a) : "l"(p));
    return a;
}

#define SWZ64(o)  ((o) ^ (((o) >> 3) & 0x30))
#define SWZ128(o) ((o) ^ (((o) >> 3) & 0x70))

#define CP16(dst, src) \
    asm volatile("cp.async.cg.shared.global [%0], [%1], 16;" :: "r"(dst), "l"(src))
#define CP_COMMIT() asm volatile("cp.async.commit_group;" ::: "memory")

#define LDSM4(r, addr) \
    asm volatile("ldmatrix.sync.aligned.m8n8.x4.shared.b16 {%0,%1,%2,%3}, [%4];" \
                 : "=r"((r)[0]), "=r"((r)[1]), "=r"((r)[2]), "=r"((r)[3]) : "r"(addr))
#define LDSM4T(r, addr) \
    asm volatile("ldmatrix.sync.aligned.m8n8.x4.trans.shared.b16 {%0,%1,%2,%3}, [%4];" \
                 : "=r"((r)[0]), "=r"((r)[1]), "=r"((r)[2]), "=r"((r)[3]) : "r"(addr))

#define MMA16816(d, a, bx, by) \
    asm volatile("mma.sync.aligned.m16n8k16.row.col.f32.bf16.bf16.f32 " \
                 "{%0,%1,%2,%3}, {%4,%5,%6,%7}, {%8,%9}, {%0,%1,%2,%3};" \
                 : "+f"((d)[0]), "+f"((d)[1]), "+f"((d)[2]), "+f"((d)[3]) \
                 : "r"((a)[0]), "r"((a)[1]), "r"((a)[2]), "r"((a)[3]), "r"(bx), "r"(by))

// pack two floats into bf16x2 hi, return hi bits, set lo bits (residual)
__device__ __forceinline__ uint32_t pack2(float a, float b, uint32_t& lo) {
    __nv_bfloat162 h = __floats2bfloat162_rn(a, b);
    __nv_bfloat162 l = __floats2bfloat162_rn(a - __bfloat162float(h.x),
                                             b - __bfloat162float(h.y));
    lo = reinterpret_cast<uint32_t&>(l);
    return reinterpret_cast<uint32_t&>(h);
}

__device__ __forceinline__ void split4(float4 v, uint2& hv, uint2& lv) {
    hv.x = pack2(v.x, v.y, lv.x);
    hv.y = pack2(v.z, v.w, lv.y);
}

// ---------------- fp32 -> bf16 hi/lo splits ----------------
__global__ void cvt_x(const float4* __restrict__ src) {
    int i = blockIdx.x * blockDim.x + threadIdx.x;
    if (i >= M_TOT * D_MODEL / 4) return;
    uint2 hv, lv;
    split4(src[i], hv, lv);
    ((uint2*)g_xh)[i] = hv;
    ((uint2*)g_xl)[i] = lv;
}

__global__ void cvt_w(const float4* __restrict__ src, int slot) {
    int i = blockIdx.x * blockDim.x + threadIdx.x;
    if (i >= DM2 / 4) return;
    uint2 hv, lv;
    split4(src[i], hv, lv);
    ((uint2*)g_wh)[(size_t)slot * (DM2 / 4) + i] = hv;
    ((uint2*)g_wl)[(size_t)slot * (DM2 / 4) + i] = lv;
}

// ---------------------------------------------------------------------------
// HMMA 3xBF16 GEMM. CTA 128x128, 8 warps (4M x 2N), K-chunk 32, cp.async x3.
// mode 0: A=g_x*, W slot z; writes bf16 hi/lo split (Q scaled 0.125) to
//         g_{q,k,v}{h,l} [B,H,S,DK].
// mode 1: A=g_ao*, W slot 3; writes fp32 row-major to outp (+bias).
// ---------------------------------------------------------------------------
__global__ __launch_bounds__(256, 2) void tc_gemm(
    int mode, const float* __restrict__ b0, const float* __restrict__ b1,
    const float* __restrict__ b2, float* outp)
{
    extern __shared__ char dsm[];
    uint32_t raw = s2u(dsm);
    const uint32_t S = (raw + 1023u) & ~1023u;

    const int tid = threadIdx.x;
    const int lane = tid & 31;
    const int wid = tid >> 5;
    const int wm = wid >> 1;
    const int wn = wid & 1;
    const int bm = blockIdx.y * 128;
    const int bn = blockIdx.x * 128;
    const int z = blockIdx.z;

    const __nv_bfloat16 *Ahp, *Alp, *Whp, *Wlp;
    const float* bias;
    if (mode == 0) {
        Ahp = g_xh; Alp = g_xl;
        Whp = g_wh + (size_t)z * DM2; Wlp = g_wl + (size_t)z * DM2;
        bias = (z == 0) ? b0 : (z == 1) ? b1 : b2;
    } else {
        Ahp = g_aoh; Alp = g_aol;
        Whp = g_wh + 3 * (size_t)DM2; Wlp = g_wl + 3 * (size_t)DM2;
        bias = b0;
    }

    const int crow = tid >> 2;
    const int ccol = (tid & 3) * 16;
    const uint32_t dst0 = SWZ64((uint32_t)(crow * 64 + ccol));
    const uint32_t dst1 = SWZ64((uint32_t)((crow + 64) * 64 + ccol));

    auto issue = [&](int stg, int kt) {
        uint32_t sb = S + (uint32_t)stg * 32768u;
        size_t ra = (size_t)(bm + crow) * D_MODEL + kt + (ccol >> 1);
        size_t rb = (size_t)(bn + crow) * D_MODEL + kt + (ccol >> 1);
        CP16(sb + dst0,          Ahp + ra);
        CP16(sb + dst1,          Ahp + ra + 64 * D_MODEL);
        CP16(sb + 8192 + dst0,   Alp + ra);
        CP16(sb + 8192 + dst1,   Alp + ra + 64 * D_MODEL);
        CP16(sb + 16384 + dst0,  Whp + rb);
        CP16(sb + 16384 + dst1,  Whp + rb + 64 * D_MODEL);
        CP16(sb + 24576 + dst0,  Wlp + rb);
        CP16(sb + 24576 + dst1,  Wlp + rb + 64 * D_MODEL);
        CP_COMMIT();
    };

    uint32_t aoff[2][2], boff[4][2];
#pragma unroll
    for (int mf = 0; mf < 2; mf++)
#pragma unroll
        for (int kh = 0; kh < 2; kh++) {
            int r = wm * 32 + mf * 16 + (lane & 15);
            aoff[mf][kh] = SWZ64((uint32_t)(r * 64 + kh * 32 + ((lane >> 4) << 4)));
        }
#pragma unroll
    for (int nf = 0; nf < 4; nf++)
#pragma unroll
        for (int kh = 0; kh < 2; kh++) {
            int r = wn * 64 + nf * 16 + (lane & 15);
            boff[nf][kh] = 16384u + SWZ64((uint32_t)(r * 64 + kh * 32 + ((lane >> 4) << 4)));
        }

    float acc[2][8][4];
#pragma unroll
    for (int mf = 0; mf < 2; mf++)
#pragma unroll
        for (int j = 0; j < 8; j++)
#pragma unroll
            for (int t = 0; t < 4; t++) acc[mf][j][t] = 0.f;

    issue(0, 0);
    issue(1, 32);

    for (int i = 0; i < 32; i++) {
        asm volatile("cp.async.wait_group 1;" ::: "memory");
        __syncthreads();
        const uint32_t sb = S + (uint32_t)(((uint32_t)i) % 3u) * 32768u;
        if (i + 2 < 32) issue((i + 2) % 3, (i + 2) * 32);
        else CP_COMMIT();

#pragma unroll
        for (int kh = 0; kh < 2; kh++) {
            uint32_t ah[2][4], al[2][4];
#pragma unroll
            for (int mf = 0; mf < 2; mf++) {
                LDSM4(ah[mf], sb + aoff[mf][kh]);
                LDSM4(al[mf], sb + 8192u + aoff[mf][kh]);
            }
#pragma unroll
            for (int nf = 0; nf < 4; nf++) {
                uint32_t bh[4], bl[4];
                LDSM4(bh, sb + boff[nf][kh]);
                LDSM4(bl, sb + 8192u + boff[nf][kh]);
#pragma unroll
                for (int mf = 0; mf < 2; mf++)
#pragma unroll
                    for (int s0 = 0; s0 < 2; s0++) {
                        const int j = nf * 2 + s0;
                        MMA16816(acc[mf][j], ah[mf], bh[s0], bh[s0 + 2]);
                        MMA16816(acc[mf][j], ah[mf], bl[s0], bl[s0 + 2]);
                        MMA16816(acc[mf][j], al[mf], bh[s0], bh[s0 + 2]);
                    }
            }
        }
    }

    const int r0 = lane >> 2;
    const int c0 = (lane & 3) << 1;
    const float scale = (mode == 0 && z == 0) ? 0.125f : 1.f;
    __nv_bfloat16* zh = (z == 0) ? g_qh : (z == 1) ? g_kh : g_vh;
    __nv_bfloat16* zl = (z == 0) ? g_ql : (z == 1) ? g_kl : g_vl;

#pragma unroll
    for (int mf = 0; mf < 2; mf++) {
        const int m_ = bm + wm * 32 + mf * 16 + r0;
#pragma unroll
        for (int j = 0; j < 8; j++) {
            const int n_ = bn + wn * 64 + j * 8 + c0;
            const float bx = bias[n_], by = bias[n_ + 1];
            float2 v0 = make_float2((acc[mf][j][0] + bx) * scale, (acc[mf][j][1] + by) * scale);
            float2 v1 = make_float2((acc[mf][j][2] + bx) * scale, (acc[mf][j][3] + by) * scale);
            if (mode == 0) {
                const int b_ = m_ >> 11, s_ = m_ & (SS - 1);
                size_t idx = ((((size_t)b_ * NH + (n_ >> 6)) * SS) + s_) * DK + (n_ & 63);
                uint32_t lo, hi;
                hi = pack2(v0.x, v0.y, lo);
                *(uint32_t*)(zh + idx) = hi;
                *(uint32_t*)(zl + idx) = lo;
                hi = pack2(v1.x, v1.y, lo);
                *(uint32_t*)(zh + idx + 8 * DK) = hi;
                *(uint32_t*)(zl + idx + 8 * DK) = lo;
            } else {
                float* p = outp + (size_t)m_ * D_MODEL + n_;
                *(float2*)p = v0;
                *(float2*)(p + 8 * D_MODEL) = v1;
            }
        }
    }
}

// ---------------------------------------------------------------------------
// Tensor-core banded flash attention. CTA = 64 queries x one (b,h), 4 warps.
// Key tiles of 64, cp.async double-buffered. 3xBF16 split for QK^T and PV.
// smem: Qh[64x64] Ql | 2 stages x (Kh,Kl,Vh,Vl each 64x64) ; 128B rows SW128.
// ---------------------------------------------------------------------------
__global__ __launch_bounds__(128, 2) void fa_attn()
{
    extern __shared__ char dsm[];
    uint32_t raw = s2u(dsm);
    const uint32_t S = (raw + 1023u) & ~1023u;

    const int tid = threadIdx.x;
    const int lane = tid & 31;
    const int wid = tid >> 5;
    const int q0 = blockIdx.x * 64;
    const int h = blockIdx.y;
    const int b = blockIdx.z;

    const size_t base = (((size_t)b * NH + h) * SS) * DK;
    const __nv_bfloat16* qh = g_qh + base;
    const __nv_bfloat16* ql = g_ql + base;
    const __nv_bfloat16* kh = g_kh + base;
    const __nv_bfloat16* kl = g_kl + base;
    const __nv_bfloat16* vh = g_vh + base;
    const __nv_bfloat16* vl = g_vl + base;

    int klo = q0 - (BAND - 1); if (klo < 0) klo = 0;
    int khi = q0 + 63 + (BAND - 1); if (khi > SS - 1) khi = SS - 1;
    const int kt_lo = klo >> 6;
    const int nt = (khi >> 6) - kt_lo + 1;

    auto issue_kv = [&](int st, int kb) {
        uint32_t sb = S + 16384u + (uint32_t)st * 32768u;
#pragma unroll
        for (int i = 0; i < 4; i++) {
            int idx = i * 128 + tid;
            int row = idx >> 3;
            int chb = (idx & 7) * 16;
            uint32_t dsw = SWZ128((uint32_t)(row * 128 + chb));
            size_t g = (size_t)(kb + row) * DK + (chb >> 1);
            CP16(sb + dsw,          kh + g);
            CP16(sb + 8192 + dsw,   kl + g);
            CP16(sb + 16384 + dsw,  vh + g);
            CP16(sb + 24576 + dsw,  vl + g);
        }
        CP_COMMIT();
    };

    // group0: Q tiles + stage0
#pragma unroll
    for (int i = 0; i < 4; i++) {
        int idx = i * 128 + tid;
        int row = idx >> 3;
        int chb = (idx & 7) * 16;
        uint32_t dsw = SWZ128((uint32_t)(row * 128 + chb));
        size_t g = (size_t)(q0 + row) * DK + (chb >> 1);
        CP16(S + dsw,        qh + g);
        CP16(S + 8192 + dsw, ql + g);
    }
    {
        uint32_t sb = S + 16384u;
        int kb = kt_lo * 64;
#pragma unroll
        for (int i = 0; i < 4; i++) {
            int idx = i * 128 + tid;
            int row = idx >> 3;
            int chb = (idx & 7) * 16;
            uint32_t dsw = SWZ128((uint32_t)(row * 128 + chb));
            size_t g = (size_t)(kb + row) * DK + (chb >> 1);
            CP16(sb + dsw,          kh + g);
            CP16(sb + 8192 + dsw,   kl + g);
            CP16(sb + 16384 + dsw,  vh + g);
            CP16(sb + 24576 + dsw,  vl + g);
        }
        CP_COMMIT();
    }
    if (nt > 1) issue_kv(1, (kt_lo + 1) * 64);

    uint32_t qfh[4][4], qfl[4][4];
    float o[8][4];
#pragma unroll
    for (int j = 0; j < 8; j++)
#pragma unroll
        for (int t = 0; t < 4; t++) o[j][t] = 0.f;
    float m0 = -1e30f, m1 = -1e30f, l0 = 0.f, l1 = 0.f;

    const int r0 = q0 + wid * 16 + (lane >> 2);

    for (int it = 0; it < nt; it++) {
        if (it + 1 < nt) asm volatile("cp.async.wait_group 1;" ::: "memory");
        else             asm volatile("cp.async.wait_group 0;" ::: "memory");
        __syncthreads();

        if (it == 0) {
            const int qr = wid * 16 + (lane & 15);
#pragma unroll
            for (int dc = 0; dc < 4; dc++) {
                uint32_t ad = SWZ128((uint32_t)(qr * 128 + dc * 32 + ((lane >> 4) << 4)));
                LDSM4(qfh[dc], S + ad);
                LDSM4(qfl[dc], S + 8192u + ad);
            }
        }

        const int kb = (kt_lo + it) * 64;
        const uint32_t kbuf  = S + 16384u + (uint32_t)(it & 1) * 32768u;
        const uint32_t klbuf = kbuf + 8192u;
        const uint32_t vbuf  = kbuf + 16384u;
        const uint32_t vlbuf = kbuf + 24576u;

        float s[8][4];
#pragma unroll
        for (int j = 0; j < 8; j++)
#pragma unroll
            for (int t = 0; t < 4; t++) s[j][t] = 0.f;

        // S = Q K^T (3-term split)
#pragma unroll
        for (int dc = 0; dc < 4; dc++) {
            const uint32_t colb = dc * 32 + ((lane >> 4) << 4);
#pragma unroll
            for (int np = 0; np < 4; np++) {
                uint32_t ad = SWZ128((uint32_t)((np * 16 + (lane & 15)) * 128 + colb));
                uint32_t bh4[4], bl4[4];
                LDSM4(bh4, kbuf + ad);
                LDSM4(bl4, klbuf + ad);
#pragma unroll
                for (int s0 = 0; s0 < 2; s0++) {
                    const int j = np * 2 + s0;
                    MMA16816(s[j], qfh[dc], bh4[s0], bh4[s0 + 2]);
                    MMA16816(s[j], qfh[dc], bl4[s0], bl4[s0 + 2]);
                    MMA16816(s[j], qfl[dc], bh4[s0], bh4[s0 + 2]);
                }
            }
        }

        // mask + online softmax
        float mt0 = -1e30f, mt1 = -1e30f;
#pragma unroll
        for (int j = 0; j < 8; j++) {
            const int kjb = kb + j * 8 + (lane & 3) * 2;
#pragma unroll
            for (int c = 0; c < 2; c++) {
                const int dq0 = r0 - (kjb + c);
                if (dq0 >= BAND || dq0 <= -BAND) s[j][c] = -1e9f;
                const int dq1 = dq0 + 8;
                if (dq1 >= BAND || dq1 <= -BAND) s[j][2 + c] = -1e9f;
                mt0 = fmaxf(mt0, s[j][c]);
                mt1 = fmaxf(mt1, s[j][2 + c]);
            }
        }
        mt0 = fmaxf(mt0, __shfl_xor_sync(0xffffffffu, mt0, 1));
        mt0 = fmaxf(mt0, __shfl_xor_sync(0xffffffffu, mt0, 2));
        mt1 = fmaxf(mt1, __shfl_xor_sync(0xffffffffu, mt1, 1));
        mt1 = fmaxf(mt1, __shfl_xor_sync(0xffffffffu, mt1, 2));
        const float mn0 = fmaxf(m0, mt0), mn1 = fmaxf(m1, mt1);
        const float a0 = __expf(m0 - mn0), a1 = __expf(m1 - mn1);
        m0 = mn0; m1 = mn1;
        float ls0 = 0.f, ls1 = 0.f;
#pragma unroll
        for (int j = 0; j < 8; j++)
#pragma unroll
            for (int c = 0; c < 2; c++) {
                float p = __expf(s[j][c] - mn0);
                s[j][c] = p; ls0 += p;
                float p2 = __expf(s[j][2 + c] - mn1);
                s[j][2 + c] = p2; ls1 += p2;
            }
        ls0 += __shfl_xor_sync(0xffffffffu, ls0, 1);
        ls0 += __shfl_xor_sync(0xffffffffu, ls0, 2);
        ls1 += __shfl_xor_sync(0xffffffffu, ls1, 1);
        ls1 += __shfl_xor_sync(0xffffffffu, ls1, 2);
        l0 = l0 * a0 + ls0;
        l1 = l1 * a1 + ls1;
#pragma unroll
        for (int j = 0; j < 8; j++) {
            o[j][0] *= a0; o[j][1] *= a0;
            o[j][2] *= a1; o[j][3] *= a1;
        }

        // O += P V (3-term split), P frags built from accum regs
#pragma unroll
        for (int kc = 0; kc < 4; kc++) {
            uint32_t ph[4], pl[4];
            ph[0] = pack2(s[2 * kc][0],     s[2 * kc][1],     pl[0]);
            ph[1] = pack2(s[2 * kc][2],     s[2 * kc][3],     pl[1]);
            ph[2] = pack2(s[2 * kc + 1][0], s[2 * kc + 1][1], pl[2]);
            ph[3] = pack2(s[2 * kc + 1][2], s[2 * kc + 1][3], pl[3]);
            const uint32_t rowb = (uint32_t)((kc * 16 + (lane & 15)) * 128 + ((lane >> 4) << 4));
#pragma unroll
            for (int dg = 0; dg < 4; dg++) {
                uint32_t ad = SWZ128(rowb + dg * 32);
                uint32_t vh4[4], vl4[4];
                LDSM4T(vh4, vbuf + ad);
                LDSM4T(vl4, vlbuf + ad);
                MMA16816(o[2 * dg],     ph, vh4[0], vh4[1]);
                MMA16816(o[2 * dg],     ph, vl4[0], vl4[1]);
                MMA16816(o[2 * dg],     pl, vh4[0], vh4[1]);
                MMA16816(o[2 * dg + 1], ph, vh4[2], vh4[3]);
                MMA16816(o[2 * dg + 1], ph, vl4[2], vl4[3]);
                MMA16816(o[2 * dg + 1], pl, vh4[2], vh4[3]);
            }
        }

        __syncthreads();
        if (it + 2 < nt) issue_kv(it & 1, (kt_lo + it + 2) * 64);
    }

    // write split output [B,S,D_MODEL]
    const float inv0 = 1.f / l0, inv1 = 1.f / l1;
    const size_t e0 = ((size_t)(b * SS) + r0) * D_MODEL + h * DK + (lane & 3) * 2;
    const size_t e1 = e0 + 8 * D_MODEL;
#pragma unroll
    for (int j = 0; j < 8; j++) {
        uint32_t lo, hi;
        hi = pack2(o[j][0] * inv0, o[j][1] * inv0, lo);
        *(uint32_t*)(g_aoh + e0 + j * 8) = hi;
        *(uint32_t*)(g_aol + e0 + j * 8) = lo;
        hi = pack2(o[j][2] * inv1, o[j][3] * inv1, lo);
        *(uint32_t*)(g_aoh + e1 + j * 8) = hi;
        *(uint32_t*)(g_aol + e1 + j * 8) = lo;
    }
}

// ---------------------------------------------------------------------------

extern "C" void kernel_launch(void* const* d_in, const int* in_sizes, int n_in,
                              void* d_out, int out_size)
{
    const float* x  = (const float*)d_in[0];
    const float* Wq = (const float*)d_in[1];
    const float* bq = (const float*)d_in[2];
    const float* Wk = (const float*)d_in[3];
    const float* bk = (const float*)d_in[4];
    const float* Wv = (const float*)d_in[5];
    const float* bv = (const float*)d_in[6];
    const float* Wo = (const float*)d_in[7];
    const float* bo = (const float*)d_in[8];
    float* out = (float*)d_out;

    const int GSM = 3 * 32768 + 1024;
    const int ASM = 16384 + 2 * 32768 + 1024;
    static bool attr_done = false;
    if (!attr_done) {
        cudaFuncSetAttribute(tc_gemm, cudaFuncAttributeMaxDynamicSharedMemorySize, GSM);
        cudaFuncSetAttribute(fa_attn, cudaFuncAttributeMaxDynamicSharedMemorySize, ASM);
        attr_done = true;
    }

    cvt_x<<<(M_TOT * D_MODEL / 4 + 255) / 256, 256>>>((const float4*)x);
    cvt_w<<<(DM2 / 4 + 255) / 256, 256>>>((const float4*)Wq, 0);
    cvt_w<<<(DM2 / 4 + 255) / 256, 256>>>((const float4*)Wk, 1);
    cvt_w<<<(DM2 / 4 + 255) / 256, 256>>>((const float4*)Wv, 2);
    cvt_w<<<(DM2 / 4 + 255) / 256, 256>>>((const float4*)Wo, 3);

    tc_gemm<<<dim3(D_MODEL / 128, M_TOT / 128, 3), 256, GSM>>>(0, bq, bk, bv, nullptr);
    fa_attn<<<dim3(SS / 64, NH, BB), 128, ASM>>>();
    tc_gemm<<<dim3(D_MODEL / 128, M_TOT / 128, 1), 256, GSM>>>(1, bo, bo, bo, out);
}

// round 5
// speedup vs baseline: 2.7699x; 1.0257x over previous
#include <cuda_runtime.h>
#include <cuda_bf16.h>
#include <cstdint>
#include <math.h>

#define D_MODEL 1024
#define NH 16
#define DK 64
#define BAND 100
#define BB 2
#define SS 2048
#define M_TOT (BB * SS)
#define DM2 (D_MODEL * D_MODEL)

// ---------------- scratch (device globals; no allocs allowed) ----------------
__device__ __align__(256) __nv_bfloat16 g_qh[BB * NH * SS * DK];
__device__ __align__(256) __nv_bfloat16 g_ql[BB * NH * SS * DK];
__device__ __align__(256) __nv_bfloat16 g_kh[BB * NH * SS * DK];
__device__ __align__(256) __nv_bfloat16 g_kl[BB * NH * SS * DK];
__device__ __align__(256) __nv_bfloat16 g_vh[BB * NH * SS * DK];
__device__ __align__(256) __nv_bfloat16 g_vl[BB * NH * SS * DK];
__device__ __align__(256) __nv_bfloat16 g_xh[M_TOT * D_MODEL];
__device__ __align__(256) __nv_bfloat16 g_xl[M_TOT * D_MODEL];
__device__ __align__(256) __nv_bfloat16 g_wh[4 * DM2];
__device__ __align__(256) __nv_bfloat16 g_wl[4 * DM2];
__device__ __align__(256) __nv_bfloat16 g_aoh[M_TOT * D_MODEL];
__device__ __align__(256) __nv_bfloat16 g_aol[M_TOT * D_MODEL];

// ---------------- helpers ----------------
__device__ __forceinline__ uint32_t s2u(const void* p) {
    uint32_t a;
    asm("{ .reg .u64 t; cvta.to.shared.u64 t, %1; cvt.u32.u64 %0, t; }" : "=r"(a) : "l"(p));
    return a;
}

#define SWZ64(o)  ((o) ^ (((o) >> 3) & 0x30))
#define SWZ128(o) ((o) ^ (((o) >> 3) & 0x70))

#define CP16(dst, src) \
    asm volatile("cp.async.cg.shared.global [%0], [%1], 16;" :: "r"(dst), "l"(src))
#define CP_COMMIT() asm volatile("cp.async.commit_group;" ::: "memory")

#define LDSM4(r, addr) \
    asm volatile("ldmatrix.sync.aligned.m8n8.x4.shared.b16 {%0,%1,%2,%3}, [%4];" \
                 : "=r"((r)[0]), "=r"((r)[1]), "=r"((r)[2]), "=r"((r)[3]) : "r"(addr))
#define LDSM4T(r, addr) \
    asm volatile("ldmatrix.sync.aligned.m8n8.x4.trans.shared.b16 {%0,%1,%2,%3}, [%4];" \
                 : "=r"((r)[0]), "=r"((r)[1]), "=r"((r)[2]), "=r"((r)[3]) : "r"(addr))

#define MMA16816(d, a, bx, by) \
    asm volatile("mma.sync.aligned.m16n8k16.row.col.f32.bf16.bf16.f32 " \
                 "{%0,%1,%2,%3}, {%4,%5,%6,%7}, {%8,%9}, {%0,%1,%2,%3};" \
                 : "+f"((d)[0]), "+f"((d)[1]), "+f"((d)[2]), "+f"((d)[3]) \
                 : "r"((a)[0]), "r"((a)[1]), "r"((a)[2]), "r"((a)[3]), "r"(bx), "r"(by))

__device__ __forceinline__ uint32_t pack2(float a, float b, uint32_t& lo) {
    __nv_bfloat162 h = __floats2bfloat162_rn(a, b);
    __nv_bfloat162 l = __floats2bfloat162_rn(a - __bfloat162float(h.x),
                                             b - __bfloat162float(h.y));
    lo = reinterpret_cast<uint32_t&>(l);
    return reinterpret_cast<uint32_t&>(h);
}

__device__ __forceinline__ void split4(float4 v, uint2& hv, uint2& lv) {
    hv.x = pack2(v.x, v.y, lv.x);
    hv.y = pack2(v.z, v.w, lv.y);
}

// ---------------- fp32 -> bf16 hi/lo splits (single launch) ----------------
#define NX4 (M_TOT * D_MODEL / 4)
#define NW4 (DM2 / 4)

__global__ void cvt_all(const float4* __restrict__ x,
                        const float4* __restrict__ wq, const float4* __restrict__ wk,
                        const float4* __restrict__ wv, const float4* __restrict__ wo)
{
    int i = blockIdx.x * blockDim.x + threadIdx.x;
    uint2 hv, lv;
    if (i < NX4) {
        split4(x[i], hv, lv);
        ((uint2*)g_xh)[i] = hv;
        ((uint2*)g_xl)[i] = lv;
    } else {
        int j = i - NX4;
        if (j >= 4 * NW4) return;
        int slot = j >> 18;            // / NW4 (262144)
        int k = j & (NW4 - 1);
        const float4* src = (slot == 0) ? wq : (slot == 1) ? wk : (slot == 2) ? wv : wo;
        split4(src[k], hv, lv);
        ((uint2*)g_wh)[j] = hv;
        ((uint2*)g_wl)[j] = lv;
    }
}

// ---------------------------------------------------------------------------
// HMMA 3xBF16 GEMM. CTA 128x128, 8 warps (4M x 2N), K-chunk 32, cp.async x3.
// ---------------------------------------------------------------------------
__global__ __launch_bounds__(256, 2) void tc_gemm(
    int mode, const float* __restrict__ b0, const float* __restrict__ b1,
    const float* __restrict__ b2, float* outp)
{
    extern __shared__ char dsm[];
    uint32_t raw = s2u(dsm);
    const uint32_t S = (raw + 1023u) & ~1023u;

    const int tid = threadIdx.x;
    const int lane = tid & 31;
    const int wid = tid >> 5;
    const int wm = wid >> 1;
    const int wn = wid & 1;
    const int bm = blockIdx.y * 128;
    const int bn = blockIdx.x * 128;
    const int z = blockIdx.z;

    const __nv_bfloat16 *Ahp, *Alp, *Whp, *Wlp;
    const float* bias;
    if (mode == 0) {
        Ahp = g_xh; Alp = g_xl;
        Whp = g_wh + (size_t)z * DM2; Wlp = g_wl + (size_t)z * DM2;
        bias = (z == 0) ? b0 : (z == 1) ? b1 : b2;
    } else {
        Ahp = g_aoh; Alp = g_aol;
        Whp = g_wh + 3 * (size_t)DM2; Wlp = g_wl + 3 * (size_t)DM2;
        bias = b0;
    }

    const int crow = tid >> 2;
    const int ccol = (tid & 3) * 16;
    const uint32_t dst0 = SWZ64((uint32_t)(crow * 64 + ccol));
    const uint32_t dst1 = SWZ64((uint32_t)((crow + 64) * 64 + ccol));

    auto issue = [&](int stg, int kt) {
        uint32_t sb = S + (uint32_t)stg * 32768u;
        size_t ra = (size_t)(bm + crow) * D_MODEL + kt + (ccol >> 1);
        size_t rb = (size_t)(bn + crow) * D_MODEL + kt + (ccol >> 1);
        CP16(sb + dst0,          Ahp + ra);
        CP16(sb + dst1,          Ahp + ra + 64 * D_MODEL);
        CP16(sb + 8192 + dst0,   Alp + ra);
        CP16(sb + 8192 + dst1,   Alp + ra + 64 * D_MODEL);
        CP16(sb + 16384 + dst0,  Whp + rb);
        CP16(sb + 16384 + dst1,  Whp + rb + 64 * D_MODEL);
        CP16(sb + 24576 + dst0,  Wlp + rb);
        CP16(sb + 24576 + dst1,  Wlp + rb + 64 * D_MODEL);
        CP_COMMIT();
    };

    uint32_t aoff[2][2], boff[4][2];
#pragma unroll
    for (int mf = 0; mf < 2; mf++)
#pragma unroll
        for (int kh = 0; kh < 2; kh++) {
            int r = wm * 32 + mf * 16 + (lane & 15);
            aoff[mf][kh] = SWZ64((uint32_t)(r * 64 + kh * 32 + ((lane >> 4) << 4)));
        }
#pragma unroll
    for (int nf = 0; nf < 4; nf++)
#pragma unroll
        for (int kh = 0; kh < 2; kh++) {
            int r = wn * 64 + nf * 16 + (lane & 15);
            boff[nf][kh] = 16384u + SWZ64((uint32_t)(r * 64 + kh * 32 + ((lane >> 4) << 4)));
        }

    float acc[2][8][4];
#pragma unroll
    for (int mf = 0; mf < 2; mf++)
#pragma unroll
        for (int j = 0; j < 8; j++)
#pragma unroll
            for (int t = 0; t < 4; t++) acc[mf][j][t] = 0.f;

    issue(0, 0);
    issue(1, 32);

    for (int i = 0; i < 32; i++) {
        asm volatile("cp.async.wait_group 1;" ::: "memory");
        __syncthreads();
        const uint32_t sb = S + (uint32_t)(((uint32_t)i) % 3u) * 32768u;
        if (i + 2 < 32) issue((i + 2) % 3, (i + 2) * 32);
        else CP_COMMIT();

#pragma unroll
        for (int kh = 0; kh < 2; kh++) {
            uint32_t ah[2][4], al[2][4];
#pragma unroll
            for (int mf = 0; mf < 2; mf++) {
                LDSM4(ah[mf], sb + aoff[mf][kh]);
                LDSM4(al[mf], sb + 8192u + aoff[mf][kh]);
            }
            // process nf in pairs; term-major MMA order for 8-wide acc reuse dist
#pragma unroll
            for (int np = 0; np < 2; np++) {
                uint32_t bh[2][4], bl[2][4];
#pragma unroll
                for (int q = 0; q < 2; q++) {
                    LDSM4(bh[q], sb + boff[np * 2 + q][kh]);
                    LDSM4(bl[q], sb + 8192u + boff[np * 2 + q][kh]);
                }
                // term 1: Ah * Bh
#pragma unroll
                for (int mf = 0; mf < 2; mf++)
#pragma unroll
                    for (int q = 0; q < 2; q++)
#pragma unroll
                        for (int s0 = 0; s0 < 2; s0++)
                            MMA16816(acc[mf][(np * 2 + q) * 2 + s0], ah[mf], bh[q][s0], bh[q][s0 + 2]);
                // term 2: Ah * Bl
#pragma unroll
                for (int mf = 0; mf < 2; mf++)
#pragma unroll
                    for (int q = 0; q < 2; q++)
#pragma unroll
                        for (int s0 = 0; s0 < 2; s0++)
                            MMA16816(acc[mf][(np * 2 + q) * 2 + s0], ah[mf], bl[q][s0], bl[q][s0 + 2]);
                // term 3: Al * Bh
#pragma unroll
                for (int mf = 0; mf < 2; mf++)
#pragma unroll
                    for (int q = 0; q < 2; q++)
#pragma unroll
                        for (int s0 = 0; s0 < 2; s0++)
                            MMA16816(acc[mf][(np * 2 + q) * 2 + s0], al[mf], bh[q][s0], bh[q][s0 + 2]);
            }
        }
    }

    const int r0 = lane >> 2;
    const int c0 = (lane & 3) << 1;
    const float scale = (mode == 0 && z == 0) ? 0.125f : 1.f;
    __nv_bfloat16* zh = (z == 0) ? g_qh : (z == 1) ? g_kh : g_vh;
    __nv_bfloat16* zl = (z == 0) ? g_ql : (z == 1) ? g_kl : g_vl;

#pragma unroll
    for (int mf = 0; mf < 2; mf++) {
        const int m_ = bm + wm * 32 + mf * 16 + r0;
#pragma unroll
        for (int j = 0; j < 8; j++) {
            const int n_ = bn + wn * 64 + j * 8 + c0;
            const float bx = bias[n_], by = bias[n_ + 1];
            float2 v0 = make_float2((acc[mf][j][0] + bx) * scale, (acc[mf][j][1] + by) * scale);
            float2 v1 = make_float2((acc[mf][j][2] + bx) * scale, (acc[mf][j][3] + by) * scale);
            if (mode == 0) {
                const int b_ = m_ >> 11, s_ = m_ & (SS - 1);
                size_t idx = ((((size_t)b_ * NH + (n_ >> 6)) * SS) + s_) * DK + (n_ & 63);
                uint32_t lo, hi;
                hi = pack2(v0.x, v0.y, lo);
                *(uint32_t*)(zh + idx) = hi;
                *(uint32_t*)(zl + idx) = lo;
                hi = pack2(v1.x, v1.y, lo);
                *(uint32_t*)(zh + idx + 8 * DK) = hi;
                *(uint32_t*)(zl + idx + 8 * DK) = lo;
            } else {
                float* p = outp + (size_t)m_ * D_MODEL + n_;
                *(float2*)p = v0;
                *(float2*)(p + 8 * D_MODEL) = v1;
            }
        }
    }
}

// ---------------------------------------------------------------------------
// Tensor-core banded flash attention with per-warp key-tile skipping.
// ---------------------------------------------------------------------------
__global__ __launch_bounds__(128, 2) void fa_attn()
{
    extern __shared__ char dsm[];
    uint32_t raw = s2u(dsm);
    const uint32_t S = (raw + 1023u) & ~1023u;

    const int tid = threadIdx.x;
    const int lane = tid & 31;
    const int wid = tid >> 5;
    const int q0 = blockIdx.x * 64;
    const int h = blockIdx.y;
    const int b = blockIdx.z;

    const size_t base = (((size_t)b * NH + h) * SS) * DK;
    const __nv_bfloat16* qh = g_qh + base;
    const __nv_bfloat16* ql = g_ql + base;
    const __nv_bfloat16* kh = g_kh + base;
    const __nv_bfloat16* kl = g_kl + base;
    const __nv_bfloat16* vh = g_vh + base;
    const __nv_bfloat16* vl = g_vl + base;

    int klo = q0 - (BAND - 1); if (klo < 0) klo = 0;
    int khi = q0 + 63 + (BAND - 1); if (khi > SS - 1) khi = SS - 1;
    const int kt_lo = klo >> 6;
    const int nt = (khi >> 6) - kt_lo + 1;

    auto issue_kv = [&](int st, int kb) {
        uint32_t sb = S + 16384u + (uint32_t)st * 32768u;
#pragma unroll
        for (int i = 0; i < 4; i++) {
            int idx = i * 128 + tid;
            int row = idx >> 3;
            int chb = (idx & 7) * 16;
            uint32_t dsw = SWZ128((uint32_t)(row * 128 + chb));
            size_t g = (size_t)(kb + row) * DK + (chb >> 1);
            CP16(sb + dsw,          kh + g);
            CP16(sb + 8192 + dsw,   kl + g);
            CP16(sb + 16384 + dsw,  vh + g);
            CP16(sb + 24576 + dsw,  vl + g);
        }
        CP_COMMIT();
    };

#pragma unroll
    for (int i = 0; i < 4; i++) {
        int idx = i * 128 + tid;
        int row = idx >> 3;
        int chb = (idx & 7) * 16;
        uint32_t dsw = SWZ128((uint32_t)(row * 128 + chb));
        size_t g = (size_t)(q0 + row) * DK + (chb >> 1);
        CP16(S + dsw,        qh + g);
        CP16(S + 8192 + dsw, ql + g);
    }
    issue_kv(0, kt_lo * 64);
    if (nt > 1) issue_kv(1, (kt_lo + 1) * 64);

    uint32_t qfh[4][4], qfl[4][4];
    float o[8][4];
#pragma unroll
    for (int j = 0; j < 8; j++)
#pragma unroll
        for (int t = 0; t < 4; t++) o[j][t] = 0.f;
    float m0 = -1e30f, m1 = -1e30f, l0 = 0.f, l1 = 0.f;

    const int wr_lo = q0 + wid * 16;
    const int r0 = wr_lo + (lane >> 2);

    for (int it = 0; it < nt; it++) {
        if (it + 1 < nt) asm volatile("cp.async.wait_group 1;" ::: "memory");
        else             asm volatile("cp.async.wait_group 0;" ::: "memory");
        __syncthreads();

        if (it == 0) {
            const int qr = wid * 16 + (lane & 15);
#pragma unroll
            for (int dc = 0; dc < 4; dc++) {
                uint32_t ad = SWZ128((uint32_t)(qr * 128 + dc * 32 + ((lane >> 4) << 4)));
                LDSM4(qfh[dc], S + ad);
                LDSM4(qfl[dc], S + 8192u + ad);
            }
        }

        const int kb = (kt_lo + it) * 64;
        // per-warp band check: warp rows [wr_lo, wr_lo+15], keys [kb, kb+63]
        const bool active = (kb < wr_lo + 15 + BAND) && (kb + 63 > wr_lo - BAND);

        if (active) {
            const uint32_t kbuf  = S + 16384u + (uint32_t)(it & 1) * 32768u;
            const uint32_t klbuf = kbuf + 8192u;
            const uint32_t vbuf  = kbuf + 16384u;
            const uint32_t vlbuf = kbuf + 24576u;

            float s[8][4];
#pragma unroll
            for (int j = 0; j < 8; j++)
#pragma unroll
                for (int t = 0; t < 4; t++) s[j][t] = 0.f;

#pragma unroll
            for (int dc = 0; dc < 4; dc++) {
                const uint32_t colb = dc * 32 + ((lane >> 4) << 4);
#pragma unroll
                for (int np = 0; np < 4; np++) {
                    uint32_t ad = SWZ128((uint32_t)((np * 16 + (lane & 15)) * 128 + colb));
                    uint32_t bh4[4], bl4[4];
                    LDSM4(bh4, kbuf + ad);
                    LDSM4(bl4, klbuf + ad);
#pragma unroll
                    for (int s0 = 0; s0 < 2; s0++)
                        MMA16816(s[np * 2 + s0], qfh[dc], bh4[s0], bh4[s0 + 2]);
#pragma unroll
                    for (int s0 = 0; s0 < 2; s0++)
                        MMA16816(s[np * 2 + s0], qfh[dc], bl4[s0], bl4[s0 + 2]);
#pragma unroll
                    for (int s0 = 0; s0 < 2; s0++)
                        MMA16816(s[np * 2 + s0], qfl[dc], bh4[s0], bh4[s0 + 2]);
                }
            }

            float mt0 = -1e30f, mt1 = -1e30f;
#pragma unroll
            for (int j = 0; j < 8; j++) {
                const int kjb = kb + j * 8 + (lane & 3) * 2;
#pragma unroll
                for (int c = 0; c < 2; c++) {
                    const int dq0 = r0 - (kjb + c);
                    if (dq0 >= BAND || dq0 <= -BAND) s[j][c] = -1e9f;
                    const int dq1 = dq0 + 8;
                    if (dq1 >= BAND || dq1 <= -BAND) s[j][2 + c] = -1e9f;
                    mt0 = fmaxf(mt0, s[j][c]);
                    mt1 = fmaxf(mt1, s[j][2 + c]);
                }
            }
            mt0 = fmaxf(mt0, __shfl_xor_sync(0xffffffffu, mt0, 1));
            mt0 = fmaxf(mt0, __shfl_xor_sync(0xffffffffu, mt0, 2));
            mt1 = fmaxf(mt1, __shfl_xor_sync(0xffffffffu, mt1, 1));
            mt1 = fmaxf(mt1, __shfl_xor_sync(0xffffffffu, mt1, 2));
            const float mn0 = fmaxf(m0, mt0), mn1 = fmaxf(m1, mt1);
            const float a0 = __expf(m0 - mn0), a1 = __expf(m1 - mn1);
            m0 = mn0; m1 = mn1;
            float ls0 = 0.f, ls1 = 0.f;
#pragma unroll
            for (int j = 0; j < 8; j++)
#pragma unroll
                for (int c = 0; c < 2; c++) {
                    float p = __expf(s[j][c] - mn0);
                    s[j][c] = p; ls0 += p;
                    float p2 = __expf(s[j][2 + c] - mn1);
                    s[j][2 + c] = p2; ls1 += p2;
                }
            ls0 += __shfl_xor_sync(0xffffffffu, ls0, 1);
            ls0 += __shfl_xor_sync(0xffffffffu, ls0, 2);
            ls1 += __shfl_xor_sync(0xffffffffu, ls1, 1);
            ls1 += __shfl_xor_sync(0xffffffffu, ls1, 2);
            l0 = l0 * a0 + ls0;
            l1 = l1 * a1 + ls1;
#pragma unroll
            for (int j = 0; j < 8; j++) {
                o[j][0] *= a0; o[j][1] *= a0;
                o[j][2] *= a1; o[j][3] *= a1;
            }

#pragma unroll
            for (int kc = 0; kc < 4; kc++) {
                uint32_t ph[4], pl[4];
                ph[0] = pack2(s[2 * kc][0],     s[2 * kc][1],     pl[0]);
                ph[1] = pack2(s[2 * kc][2],     s[2 * kc][3],     pl[1]);
                ph[2] = pack2(s[2 * kc + 1][0], s[2 * kc + 1][1], pl[2]);
                ph[3] = pack2(s[2 * kc + 1][2], s[2 * kc + 1][3], pl[3]);
                const uint32_t rowb = (uint32_t)((kc * 16 + (lane & 15)) * 128 + ((lane >> 4) << 4));
#pragma unroll
                for (int dg = 0; dg < 4; dg++) {
                    uint32_t ad = SWZ128(rowb + dg * 32);
                    uint32_t vh4[4], vl4[4];
                    LDSM4T(vh4, vbuf + ad);
                    LDSM4T(vl4, vlbuf + ad);
                    MMA16816(o[2 * dg],     ph, vh4[0], vh4[1]);
                    MMA16816(o[2 * dg + 1], ph, vh4[2], vh4[3]);
                    MMA16816(o[2 * dg],     ph, vl4[0], vl4[1]);
                    MMA16816(o[2 * dg + 1], ph, vl4[2], vl4[3]);
                    MMA16816(o[2 * dg],     pl, vh4[0], vh4[1]);
                    MMA16816(o[2 * dg + 1], pl, vh4[2], vh4[3]);
                }
            }
        }

        __syncthreads();
        if (it + 2 < nt) issue_kv(it & 1, (kt_lo + it + 2) * 64);
    }

    const float inv0 = 1.f / l0, inv1 = 1.f / l1;
    const size_t e0 = ((size_t)(b * SS) + r0) * D_MODEL + h * DK + (lane & 3) * 2;
    const size_t e1 = e0 + 8 * D_MODEL;
#pragma unroll
    for (int j = 0; j < 8; j++) {
        uint32_t lo, hi;
        hi = pack2(o[j][0] * inv0, o[j][1] * inv0, lo);
        *(uint32_t*)(g_aoh + e0 + j * 8) = hi;
        *(uint32_t*)(g_aol + e0 + j * 8) = lo;
        hi = pack2(o[j][2] * inv1, o[j][3] * inv1, lo);
        *(uint32_t*)(g_aoh + e1 + j * 8) = hi;
        *(uint32_t*)(g_aol + e1 + j * 8) = lo;
    }
}

// ---------------------------------------------------------------------------

extern "C" void kernel_launch(void* const* d_in, const int* in_sizes, int n_in,
                              void* d_out, int out_size)
{
    const float* x  = (const float*)d_in[0];
    const float* Wq = (const float*)d_in[1];
    const float* bq = (const float*)d_in[2];
    const float* Wk = (const float*)d_in[3];
    const float* bk = (const float*)d_in[4];
    const float* Wv = (const float*)d_in[5];
    const float* bv = (const float*)d_in[6];
    const float* Wo = (const float*)d_in[7];
    const float* bo = (const float*)d_in[8];
    float* out = (float*)d_out;

    const int GSM = 3 * 32768 + 1024;
    const int ASM = 16384 + 2 * 32768 + 1024;
    static bool attr_done = false;
    if (!attr_done) {
        cudaFuncSetAttribute(tc_gemm, cudaFuncAttributeMaxDynamicSharedMemorySize, GSM);
        cudaFuncSetAttribute(fa_attn, cudaFuncAttributeMaxDynamicSharedMemorySize, ASM);
        attr_done = true;
    }

    const int NCVT = NX4 + 4 * NW4;
    cvt_all<<<(NCVT + 255) / 256, 256>>>((const float4*)x, (const float4*)Wq,
                                         (const float4*)Wk, (const float4*)Wv,
                                         (const float4*)Wo);

    tc_gemm<<<dim3(D_MODEL / 128, M_TOT / 128, 3), 256, GSM>>>(0, bq, bk, bv, nullptr);
    fa_attn<<<dim3(SS / 64, NH, BB), 128, ASM>>>();
    tc_gemm<<<dim3(D_MODEL / 128, M_TOT / 128, 1), 256, GSM>>>(1, bo, bo, bo, out);
}

// round 6
// speedup vs baseline: 2.8635x; 1.0338x over previous
#include <cuda_runtime.h>
#include <cuda_bf16.h>
#include <cstdint>
#include <math.h>

#define D_MODEL 1024
#define NH 16
#define DK 64
#define BAND 100
#define BB 2
#define SS 2048
#define M_TOT (BB * SS)
#define DM2 (D_MODEL * D_MODEL)

// ---------------- scratch (device globals; no allocs allowed) ----------------
__device__ __align__(256) __nv_bfloat16 g_qh[BB * NH * SS * DK];
__device__ __align__(256) __nv_bfloat16 g_ql[BB * NH * SS * DK];
__device__ __align__(256) __nv_bfloat16 g_kh[BB * NH * SS * DK];
__device__ __align__(256) __nv_bfloat16 g_kl[BB * NH * SS * DK];
__device__ __align__(256) __nv_bfloat16 g_vh[BB * NH * SS * DK];
__device__ __align__(256) __nv_bfloat16 g_vl[BB * NH * SS * DK];
__device__ __align__(256) __nv_bfloat16 g_xh[M_TOT * D_MODEL];
__device__ __align__(256) __nv_bfloat16 g_xl[M_TOT * D_MODEL];
__device__ __align__(256) __nv_bfloat16 g_wh[4 * DM2];
__device__ __align__(256) __nv_bfloat16 g_wl[4 * DM2];
__device__ __align__(256) __nv_bfloat16 g_aoh[M_TOT * D_MODEL];
__device__ __align__(256) __nv_bfloat16 g_aol[M_TOT * D_MODEL];

// ---------------- helpers ----------------
__device__ __forceinline__ uint32_t s2u(const void* p) {
    uint32_t a;
    asm("{ .reg .u64 t; cvta.to.shared.u64 t, %1; cvt.u32.u64 %0, t; }" : "=r"(a) : "l"(p));
    return a;
}

#define SWZ64(o)  ((o) ^ (((o) >> 3) & 0x30))
#define SWZ128(o) ((o) ^ (((o) >> 3) & 0x70))

#define CP16(dst, src) \
    asm volatile("cp.async.cg.shared.global [%0], [%1], 16;" :: "r"(dst), "l"(src))
#define CP_COMMIT() asm volatile("cp.async.commit_group;" ::: "memory")

#define LDSM4(r, addr) \
    asm volatile("ldmatrix.sync.aligned.m8n8.x4.shared.b16 {%0,%1,%2,%3}, [%4];" \
                 : "=r"((r)[0]), "=r"((r)[1]), "=r"((r)[2]), "=r"((r)[3]) : "r"(addr))
#define LDSM4T(r, addr) \
    asm volatile("ldmatrix.sync.aligned.m8n8.x4.trans.shared.b16 {%0,%1,%2,%3}, [%4];" \
                 : "=r"((r)[0]), "=r"((r)[1]), "=r"((r)[2]), "=r"((r)[3]) : "r"(addr))

#define MMA16816(d, a, bx, by) \
    asm volatile("mma.sync.aligned.m16n8k16.row.col.f32.bf16.bf16.f32 " \
                 "{%0,%1,%2,%3}, {%4,%5,%6,%7}, {%8,%9}, {%0,%1,%2,%3};" \
                 : "+f"((d)[0]), "+f"((d)[1]), "+f"((d)[2]), "+f"((d)[3]) \
                 : "r"((a)[0]), "r"((a)[1]), "r"((a)[2]), "r"((a)[3]), "r"(bx), "r"(by))

__device__ __forceinline__ uint32_t pack2(float a, float b, uint32_t& lo) {
    __nv_bfloat162 h = __floats2bfloat162_rn(a, b);
    __nv_bfloat162 l = __floats2bfloat162_rn(a - __bfloat162float(h.x),
                                             b - __bfloat162float(h.y));
    lo = reinterpret_cast<uint32_t&>(l);
    return reinterpret_cast<uint32_t&>(h);
}

__device__ __forceinline__ void split4(float4 v, uint2& hv, uint2& lv) {
    hv.x = pack2(v.x, v.y, lv.x);
    hv.y = pack2(v.z, v.w, lv.y);
}

// ---------------- fp32 -> bf16 hi/lo splits (single launch) ----------------
#define NX4 (M_TOT * D_MODEL / 4)
#define NW4 (DM2 / 4)

__global__ void cvt_all(const float4* __restrict__ x,
                        const float4* __restrict__ wq, const float4* __restrict__ wk,
                        const float4* __restrict__ wv, const float4* __restrict__ wo)
{
    int i = blockIdx.x * blockDim.x + threadIdx.x;
    uint2 hv, lv;
    if (i < NX4) {
        split4(x[i], hv, lv);
        ((uint2*)g_xh)[i] = hv;
        ((uint2*)g_xl)[i] = lv;
    } else {
        int j = i - NX4;
        if (j >= 4 * NW4) return;
        int slot = j >> 18;
        int k = j & (NW4 - 1);
        const float4* src = (slot == 0) ? wq : (slot == 1) ? wk : (slot == 2) ? wv : wo;
        split4(src[k], hv, lv);
        ((uint2*)g_wh)[j] = hv;
        ((uint2*)g_wl)[j] = lv;
    }
}

// ---------------------------------------------------------------------------
// HMMA 3xBF16 GEMM. CTA 128x64, 8 warps (4M x 2N, warp tile 32x32),
// K-chunk 32, cp.async 3-stage, 3 CTAs/SM.
// stage layout: Ah[128x64B]@0  Al@8192  Bh[64x64B]@16384  Bl@20480  (24576 B)
// ---------------------------------------------------------------------------
__global__ __launch_bounds__(256, 3) void tc_gemm(
    int mode, const float* __restrict__ b0, const float* __restrict__ b1,
    const float* __restrict__ b2, float* outp)
{
    extern __shared__ char dsm[];
    uint32_t raw = s2u(dsm);
    const uint32_t S = (raw + 1023u) & ~1023u;

    const int tid = threadIdx.x;
    const int lane = tid & 31;
    const int wid = tid >> 5;
    const int wm = wid >> 1;
    const int wn = wid & 1;
    const int bm = blockIdx.y * 128;
    const int bn = blockIdx.x * 64;
    const int z = blockIdx.z;

    const __nv_bfloat16 *Ahp, *Alp, *Whp, *Wlp;
    const float* bias;
    if (mode == 0) {
        Ahp = g_xh; Alp = g_xl;
        Whp = g_wh + (size_t)z * DM2; Wlp = g_wl + (size_t)z * DM2;
        bias = (z == 0) ? b0 : (z == 1) ? b1 : b2;
    } else {
        Ahp = g_aoh; Alp = g_aol;
        Whp = g_wh + 3 * (size_t)DM2; Wlp = g_wl + 3 * (size_t)DM2;
        bias = b0;
    }

    const int crow = tid >> 2;               // 0..63
    const int ccol = (tid & 3) * 16;
    const uint32_t dst0 = SWZ64((uint32_t)(crow * 64 + ccol));
    const uint32_t dst1 = SWZ64((uint32_t)((crow + 64) * 64 + ccol));

    auto issue = [&](int stg, int kt) {
        uint32_t sb = S + (uint32_t)stg * 24576u;
        size_t ra = (size_t)(bm + crow) * D_MODEL + kt + (ccol >> 1);
        size_t rb = (size_t)(bn + crow) * D_MODEL + kt + (ccol >> 1);
        CP16(sb + dst0,          Ahp + ra);
        CP16(sb + dst1,          Ahp + ra + 64 * D_MODEL);
        CP16(sb + 8192 + dst0,   Alp + ra);
        CP16(sb + 8192 + dst1,   Alp + ra + 64 * D_MODEL);
        CP16(sb + 16384 + dst0,  Whp + rb);
        CP16(sb + 20480 + dst0,  Wlp + rb);
        CP_COMMIT();
    };

    uint32_t aoff[2][2], boff[2][2];
#pragma unroll
    for (int mf = 0; mf < 2; mf++)
#pragma unroll
        for (int kh = 0; kh < 2; kh++) {
            int r = wm * 32 + mf * 16 + (lane & 15);
            aoff[mf][kh] = SWZ64((uint32_t)(r * 64 + kh * 32 + ((lane >> 4) << 4)));
        }
#pragma unroll
    for (int nf = 0; nf < 2; nf++)
#pragma unroll
        for (int kh = 0; kh < 2; kh++) {
            int r = wn * 32 + nf * 16 + (lane & 15);
            boff[nf][kh] = 16384u + SWZ64((uint32_t)(r * 64 + kh * 32 + ((lane >> 4) << 4)));
        }

    float acc[2][4][4];
#pragma unroll
    for (int mf = 0; mf < 2; mf++)
#pragma unroll
        for (int j = 0; j < 4; j++)
#pragma unroll
            for (int t = 0; t < 4; t++) acc[mf][j][t] = 0.f;

    issue(0, 0);
    issue(1, 32);

    for (int i = 0; i < 32; i++) {
        asm volatile("cp.async.wait_group 1;" ::: "memory");
        __syncthreads();
        const uint32_t sb = S + (uint32_t)(((uint32_t)i) % 3u) * 24576u;
        if (i + 2 < 32) issue((i + 2) % 3, (i + 2) * 32);
        else CP_COMMIT();

#pragma unroll
        for (int kh = 0; kh < 2; kh++) {
            uint32_t ah[2][4], al[2][4];
#pragma unroll
            for (int mf = 0; mf < 2; mf++) {
                LDSM4(ah[mf], sb + aoff[mf][kh]);
                LDSM4(al[mf], sb + 8192u + aoff[mf][kh]);
            }
#pragma unroll
            for (int nf = 0; nf < 2; nf++) {
                uint32_t bh[4], bl[4];
                LDSM4(bh, sb + boff[nf][kh]);
                LDSM4(bl, sb + 4096u + boff[nf][kh]);
                // term-major (reuse distance 4; warp-level parallelism covers latency)
#pragma unroll
                for (int mf = 0; mf < 2; mf++)
#pragma unroll
                    for (int s0 = 0; s0 < 2; s0++)
                        MMA16816(acc[mf][nf * 2 + s0], ah[mf], bh[s0], bh[s0 + 2]);
#pragma unroll
                for (int mf = 0; mf < 2; mf++)
#pragma unroll
                    for (int s0 = 0; s0 < 2; s0++)
                        MMA16816(acc[mf][nf * 2 + s0], ah[mf], bl[s0], bl[s0 + 2]);
#pragma unroll
                for (int mf = 0; mf < 2; mf++)
#pragma unroll
                    for (int s0 = 0; s0 < 2; s0++)
                        MMA16816(acc[mf][nf * 2 + s0], al[mf], bh[s0], bh[s0 + 2]);
            }
        }
    }

    const int r0 = lane >> 2;
    const int c0 = (lane & 3) << 1;
    const float scale = (mode == 0 && z == 0) ? 0.125f : 1.f;
    __nv_bfloat16* zh = (z == 0) ? g_qh : (z == 1) ? g_kh : g_vh;
    __nv_bfloat16* zl = (z == 0) ? g_ql : (z == 1) ? g_kl : g_vl;

#pragma unroll
    for (int mf = 0; mf < 2; mf++) {
        const int m_ = bm + wm * 32 + mf * 16 + r0;
#pragma unroll
        for (int j = 0; j < 4; j++) {
            const int n_ = bn + wn * 32 + j * 8 + c0;
            const float bx = bias[n_], by = bias[n_ + 1];
            float2 v0 = make_float2((acc[mf][j][0] + bx) * scale, (acc[mf][j][1] + by) * scale);
            float2 v1 = make_float2((acc[mf][j][2] + bx) * scale, (acc[mf][j][3] + by) * scale);
            if (mode == 0) {
                const int b_ = m_ >> 11, s_ = m_ & (SS - 1);
                size_t idx = ((((size_t)b_ * NH + (n_ >> 6)) * SS) + s_) * DK + (n_ & 63);
                uint32_t lo, hi;
                hi = pack2(v0.x, v0.y, lo);
                *(uint32_t*)(zh + idx) = hi;
                *(uint32_t*)(zl + idx) = lo;
                hi = pack2(v1.x, v1.y, lo);
                *(uint32_t*)(zh + idx + 8 * DK) = hi;
                *(uint32_t*)(zl + idx + 8 * DK) = lo;
            } else {
                float* p = outp + (size_t)m_ * D_MODEL + n_;
                *(float2*)p = v0;
                *(float2*)(p + 8 * D_MODEL) = v1;
            }
        }
    }
}

// ---------------------------------------------------------------------------
// Tensor-core banded flash attention with per-warp key-tile skipping.
// ---------------------------------------------------------------------------
__global__ __launch_bounds__(128, 2) void fa_attn()
{
    extern __shared__ char dsm[];
    uint32_t raw = s2u(dsm);
    const uint32_t S = (raw + 1023u) & ~1023u;

    const int tid = threadIdx.x;
    const int lane = tid & 31;
    const int wid = tid >> 5;
    const int q0 = blockIdx.x * 64;
    const int h = blockIdx.y;
    const int b = blockIdx.z;

    const size_t base = (((size_t)b * NH + h) * SS) * DK;
    const __nv_bfloat16* qh = g_qh + base;
    const __nv_bfloat16* ql = g_ql + base;
    const __nv_bfloat16* kh = g_kh + base;
    const __nv_bfloat16* kl = g_kl + base;
    const __nv_bfloat16* vh = g_vh + base;
    const __nv_bfloat16* vl = g_vl + base;

    int klo = q0 - (BAND - 1); if (klo < 0) klo = 0;
    int khi = q0 + 63 + (BAND - 1); if (khi > SS - 1) khi = SS - 1;
    const int kt_lo = klo >> 6;
    const int nt = (khi >> 6) - kt_lo + 1;

    auto issue_kv = [&](int st, int kb) {
        uint32_t sb = S + 16384u + (uint32_t)st * 32768u;
#pragma unroll
        for (int i = 0; i < 4; i++) {
            int idx = i * 128 + tid;
            int row = idx >> 3;
            int chb = (idx & 7) * 16;
            uint32_t dsw = SWZ128((uint32_t)(row * 128 + chb));
            size_t g = (size_t)(kb + row) * DK + (chb >> 1);
            CP16(sb + dsw,          kh + g);
            CP16(sb + 8192 + dsw,   kl + g);
            CP16(sb + 16384 + dsw,  vh + g);
            CP16(sb + 24576 + dsw,  vl + g);
        }
        CP_COMMIT();
    };

#pragma unroll
    for (int i = 0; i < 4; i++) {
        int idx = i * 128 + tid;
        int row = idx >> 3;
        int chb = (idx & 7) * 16;
        uint32_t dsw = SWZ128((uint32_t)(row * 128 + chb));
        size_t g = (size_t)(q0 + row) * DK + (chb >> 1);
        CP16(S + dsw,        qh + g);
        CP16(S + 8192 + dsw, ql + g);
    }
    issue_kv(0, kt_lo * 64);
    if (nt > 1) issue_kv(1, (kt_lo + 1) * 64);

    uint32_t qfh[4][4], qfl[4][4];
    float o[8][4];
#pragma unroll
    for (int j = 0; j < 8; j++)
#pragma unroll
        for (int t = 0; t < 4; t++) o[j][t] = 0.f;
    float m0 = -1e30f, m1 = -1e30f, l0 = 0.f, l1 = 0.f;

    const int wr_lo = q0 + wid * 16;
    const int r0 = wr_lo + (lane >> 2);

    for (int it = 0; it < nt; it++) {
        if (it + 1 < nt) asm volatile("cp.async.wait_group 1;" ::: "memory");
        else             asm volatile("cp.async.wait_group 0;" ::: "memory");
        __syncthreads();

        if (it == 0) {
            const int qr = wid * 16 + (lane & 15);
#pragma unroll
            for (int dc = 0; dc < 4; dc++) {
                uint32_t ad = SWZ128((uint32_t)(qr * 128 + dc * 32 + ((lane >> 4) << 4)));
                LDSM4(qfh[dc], S + ad);
                LDSM4(qfl[dc], S + 8192u + ad);
            }
        }

        const int kb = (kt_lo + it) * 64;
        const bool active = (kb < wr_lo + 15 + BAND) && (kb + 63 > wr_lo - BAND);

        if (active) {
            const uint32_t kbuf  = S + 16384u + (uint32_t)(it & 1) * 32768u;
            const uint32_t klbuf = kbuf + 8192u;
            const uint32_t vbuf  = kbuf + 16384u;
            const uint32_t vlbuf = kbuf + 24576u;

            float s[8][4];
#pragma unroll
            for (int j = 0; j < 8; j++)
#pragma unroll
                for (int t = 0; t < 4; t++) s[j][t] = 0.f;

#pragma unroll
            for (int dc = 0; dc < 4; dc++) {
                const uint32_t colb = dc * 32 + ((lane >> 4) << 4);
#pragma unroll
                for (int np = 0; np < 4; np++) {
                    uint32_t ad = SWZ128((uint32_t)((np * 16 + (lane & 15)) * 128 + colb));
                    uint32_t bh4[4], bl4[4];
                    LDSM4(bh4, kbuf + ad);
                    LDSM4(bl4, klbuf + ad);
#pragma unroll
                    for (int s0 = 0; s0 < 2; s0++)
                        MMA16816(s[np * 2 + s0], qfh[dc], bh4[s0], bh4[s0 + 2]);
#pragma unroll
                    for (int s0 = 0; s0 < 2; s0++)
                        MMA16816(s[np * 2 + s0], qfh[dc], bl4[s0], bl4[s0 + 2]);
#pragma unroll
                    for (int s0 = 0; s0 < 2; s0++)
                        MMA16816(s[np * 2 + s0], qfl[dc], bh4[s0], bh4[s0 + 2]);
                }
            }

            float mt0 = -1e30f, mt1 = -1e30f;
#pragma unroll
            for (int j = 0; j < 8; j++) {
                const int kjb = kb + j * 8 + (lane & 3) * 2;
#pragma unroll
                for (int c = 0; c < 2; c++) {
                    const int dq0 = r0 - (kjb + c);
                    if (dq0 >= BAND || dq0 <= -BAND) s[j][c] = -1e9f;
                    const int dq1 = dq0 + 8;
                    if (dq1 >= BAND || dq1 <= -BAND) s[j][2 + c] = -1e9f;
                    mt0 = fmaxf(mt0, s[j][c]);
                    mt1 = fmaxf(mt1, s[j][2 + c]);
                }
            }
            mt0 = fmaxf(mt0, __shfl_xor_sync(0xffffffffu, mt0, 1));
            mt0 = fmaxf(mt0, __shfl_xor_sync(0xffffffffu, mt0, 2));
            mt1 = fmaxf(mt1, __shfl_xor_sync(0xffffffffu, mt1, 1));
            mt1 = fmaxf(mt1, __shfl_xor_sync(0xffffffffu, mt1, 2));
            const float mn0 = fmaxf(m0, mt0), mn1 = fmaxf(m1, mt1);
            const float a0 = __expf(m0 - mn0), a1 = __expf(m1 - mn1);
            m0 = mn0; m1 = mn1;
            float ls0 = 0.f, ls1 = 0.f;
#pragma unroll
            for (int j = 0; j < 8; j++)
#pragma unroll
                for (int c = 0; c < 2; c++) {
                    float p = __expf(s[j][c] - mn0);
                    s[j][c] = p; ls0 += p;
                    float p2 = __expf(s[j][2 + c] - mn1);
                    s[j][2 + c] = p2; ls1 += p2;
                }
            ls0 += __shfl_xor_sync(0xffffffffu, ls0, 1);
            ls0 += __shfl_xor_sync(0xffffffffu, ls0, 2);
            ls1 += __shfl_xor_sync(0xffffffffu, ls1, 1);
            ls1 += __shfl_xor_sync(0xffffffffu, ls1, 2);
            l0 = l0 * a0 + ls0;
            l1 = l1 * a1 + ls1;
#pragma unroll
            for (int j = 0; j < 8; j++) {
                o[j][0] *= a0; o[j][1] *= a0;
                o[j][2] *= a1; o[j][3] *= a1;
            }

#pragma unroll
            for (int kc = 0; kc < 4; kc++) {
                uint32_t ph[4], pl[4];
                ph[0] = pack2(s[2 * kc][0],     s[2 * kc][1],     pl[0]);
                ph[1] = pack2(s[2 * kc][2],     s[2 * kc][3],     pl[1]);
                ph[2] = pack2(s[2 * kc + 1][0], s[2 * kc + 1][1], pl[2]);
                ph[3] = pack2(s[2 * kc + 1][2], s[2 * kc + 1][3], pl[3]);
                const uint32_t rowb = (uint32_t)((kc * 16 + (lane & 15)) * 128 + ((lane >> 4) << 4));
#pragma unroll
                for (int dg = 0; dg < 4; dg++) {
                    uint32_t ad = SWZ128(rowb + dg * 32);
                    uint32_t vh4[4], vl4[4];
                    LDSM4T(vh4, vbuf + ad);
                    LDSM4T(vl4, vlbuf + ad);
                    MMA16816(o[2 * dg],     ph, vh4[0], vh4[1]);
                    MMA16816(o[2 * dg + 1], ph, vh4[2], vh4[3]);
                    MMA16816(o[2 * dg],     ph, vl4[0], vl4[1]);
                    MMA16816(o[2 * dg + 1], ph, vl4[2], vl4[3]);
                    MMA16816(o[2 * dg],     pl, vh4[0], vh4[1]);
                    MMA16816(o[2 * dg + 1], pl, vh4[2], vh4[3]);
                }
            }
        }

        __syncthreads();
        if (it + 2 < nt) issue_kv(it & 1, (kt_lo + it + 2) * 64);
    }

    const float inv0 = 1.f / l0, inv1 = 1.f / l1;
    const size_t e0 = ((size_t)(b * SS) + r0) * D_MODEL + h * DK + (lane & 3) * 2;
    const size_t e1 = e0 + 8 * D_MODEL;
#pragma unroll
    for (int j = 0; j < 8; j++) {
        uint32_t lo, hi;
        hi = pack2(o[j][0] * inv0, o[j][1] * inv0, lo);
        *(uint32_t*)(g_aoh + e0 + j * 8) = hi;
        *(uint32_t*)(g_aol + e0 + j * 8) = lo;
        hi = pack2(o[j][2] * inv1, o[j][3] * inv1, lo);
        *(uint32_t*)(g_aoh + e1 + j * 8) = hi;
        *(uint32_t*)(g_aol + e1 + j * 8) = lo;
    }
}

// ---------------------------------------------------------------------------

extern "C" void kernel_launch(void* const* d_in, const int* in_sizes, int n_in,
                              void* d_out, int out_size)
{
    const float* x  = (const float*)d_in[0];
    const float* Wq = (const float*)d_in[1];
    const float* bq = (const float*)d_in[2];
    const float* Wk = (const float*)d_in[3];
    const float* bk = (const float*)d_in[4];
    const float* Wv = (const float*)d_in[5];
    const float* bv = (const float*)d_in[6];
    const float* Wo = (const float*)d_in[7];
    const float* bo = (const float*)d_in[8];
    float* out = (float*)d_out;

    const int GSM = 3 * 24576 + 1024;   // 74752 B per CTA, 3 CTAs/SM
    const int ASM = 16384 + 2 * 32768 + 1024;
    static bool attr_done = false;
    if (!attr_done) {
        cudaFuncSetAttribute(tc_gemm, cudaFuncAttributeMaxDynamicSharedMemorySize, GSM);
        cudaFuncSetAttribute(fa_attn, cudaFuncAttributeMaxDynamicSharedMemorySize, ASM);
        attr_done = true;
    }

    const int NCVT = NX4 + 4 * NW4;
    cvt_all<<<(NCVT + 255) / 256, 256>>>((const float4*)x, (const float4*)Wq,
                                         (const float4*)Wk, (const float4*)Wv,
                                         (const float4*)Wo);

    tc_gemm<<<dim3(D_MODEL / 64, M_TOT / 128, 3), 256, GSM>>>(0, bq, bk, bv, nullptr);
    fa_attn<<<dim3(SS / 64, NH, BB), 128, ASM>>>();
    tc_gemm<<<dim3(D_MODEL / 64, M_TOT / 128, 1), 256, GSM>>>(1, bo, bo, bo, out);
}